// round 5
// baseline (speedup 1.0000x reference)
#include <cuda_runtime.h>
#include <cuda_bf16.h>
#include <math.h>

// ---------------- problem constants ----------------
#define BATCH   4
#define NSEQ    2304          // 48*48
#define CDIM    256
#define NHEADS  4
#define DH      64
#define HIMG    48
#define WIMG    48
#define MROWS   (BATCH*NSEQ)          // 9216
#define QS      (BATCH*NHEADS*NSEQ*DH) // 2359296 per q/k/v

// ---------------- scratch (device globals; no cudaMalloc allowed) ----------------
__device__ float g_qkv[3ull*QS];          // [sel][b*h][n][64]
__device__ float g_attn[(size_t)MROWS*CDIM];
__device__ float g_x1[(size_t)MROWS*CDIM];
__device__ float g_x2[(size_t)MROWS*CDIM];
__device__ float g_h[(size_t)MROWS*4*CDIM];

// ---------------- generic SGEMM: C = A(MxK) * B(NxK)^T, epilogues ----------------
// EPI 0: qkv + rope -> scatter into g_qkv layout
// EPI 1: + residual (res[m][n])
// EPI 2: + bias, exact gelu
// EPI 3: + bias + residual
#define BKK 16

template<int EPI>
__global__ __launch_bounds__(256) void sgemm_kernel(
    const float* __restrict__ A, const float* __restrict__ B, float* __restrict__ C,
    int M, int N, int K,
    const float* __restrict__ bias, const float* __restrict__ res)
{
    __shared__ float As[BKK][128];
    __shared__ float Bs[BKK][128];

    const int tid = threadIdx.x;
    const int m0 = blockIdx.y * 128;
    const int n0 = blockIdx.x * 128;

    const int lr = tid >> 1;          // row in tile (0..127)
    const int lk = (tid & 1) * 8;     // k offset (0 or 8)

    const float* Arow = A + (size_t)(m0 + lr) * K + lk;
    const float* Brow = B + (size_t)(n0 + lr) * K + lk;

    const int r0 = (tid >> 4) * 8;
    const int c0 = (tid & 15) * 8;

    float acc[8][8];
#pragma unroll
    for (int i = 0; i < 8; ++i)
#pragma unroll
        for (int j = 0; j < 8; ++j) acc[i][j] = 0.f;

    float4 pa0 = *(const float4*)(Arow);
    float4 pa1 = *(const float4*)(Arow + 4);
    float4 pb0 = *(const float4*)(Brow);
    float4 pb1 = *(const float4*)(Brow + 4);

    int kk = 0;
    while (true) {
        As[lk+0][lr]=pa0.x; As[lk+1][lr]=pa0.y; As[lk+2][lr]=pa0.z; As[lk+3][lr]=pa0.w;
        As[lk+4][lr]=pa1.x; As[lk+5][lr]=pa1.y; As[lk+6][lr]=pa1.z; As[lk+7][lr]=pa1.w;
        Bs[lk+0][lr]=pb0.x; Bs[lk+1][lr]=pb0.y; Bs[lk+2][lr]=pb0.z; Bs[lk+3][lr]=pb0.w;
        Bs[lk+4][lr]=pb1.x; Bs[lk+5][lr]=pb1.y; Bs[lk+6][lr]=pb1.z; Bs[lk+7][lr]=pb1.w;
        __syncthreads();

        kk += BKK;
        const bool more = (kk < K);
        if (more) {
            pa0 = *(const float4*)(Arow + kk);
            pa1 = *(const float4*)(Arow + kk + 4);
            pb0 = *(const float4*)(Brow + kk);
            pb1 = *(const float4*)(Brow + kk + 4);
        }

#pragma unroll
        for (int p = 0; p < BKK; ++p) {
            float4 a0 = *(const float4*)(&As[p][r0]);
            float4 a1 = *(const float4*)(&As[p][r0 + 4]);
            float4 b0 = *(const float4*)(&Bs[p][c0]);
            float4 b1 = *(const float4*)(&Bs[p][c0 + 4]);
            float ar[8] = {a0.x,a0.y,a0.z,a0.w,a1.x,a1.y,a1.z,a1.w};
            float br[8] = {b0.x,b0.y,b0.z,b0.w,b1.x,b1.y,b1.z,b1.w};
#pragma unroll
            for (int i = 0; i < 8; ++i)
#pragma unroll
                for (int j = 0; j < 8; ++j)
                    acc[i][j] = fmaf(ar[i], br[j], acc[i][j]);
        }
        if (!more) break;
        __syncthreads();
    }

    // ---------------- epilogues ----------------
    if (EPI == 0) {
        // qkv + rope, scatter to g_qkv [sel][(b*4+h)][pos][d]
#pragma unroll
        for (int i = 0; i < 8; ++i) {
            int m = m0 + r0 + i;
            int b = m / NSEQ;
            int pos = m - b * NSEQ;
            int yy = pos / WIMG;
            int xx = pos - yy * WIMG;
#pragma unroll
            for (int j = 0; j < 8; j += 2) {
                int c = n0 + c0 + j;
                int sel = c >> 8;
                int rem = c & 255;
                int h = rem >> 6;
                int d = rem & 63;
                float v0 = acc[i][j], v1 = acc[i][j+1];
                if (sel < 2) {
                    float coord = (d < 32) ? (float)yy : (float)xx;
                    int j0 = d & 31;
                    // inv_freq = 10000^(-j/32) = 2^(-j*log2(1e4)/32)
                    float f0 = exp2f(-(float)j0 * 0.41524101186f);
                    float f1 = exp2f(-(float)(j0 + 1) * 0.41524101186f);
                    float s0, cv0, s1, cv1;
                    sincosf(coord * f0, &s0, &cv0);
                    sincosf(coord * f1, &s1, &cv1);
                    float w0 = v0 * cv0 - v1 * s0;
                    float w1 = v1 * cv1 + v0 * s1;
                    v0 = w0; v1 = w1;
                }
                size_t base = (size_t)sel * QS + ((size_t)(b * NHEADS + h) * NSEQ + pos) * DH + d;
                C[base]     = v0;
                C[base + 1] = v1;
            }
        }
    } else {
#pragma unroll
        for (int i = 0; i < 8; ++i) {
            int m = m0 + r0 + i;
            float* crow = C + (size_t)m * N + n0 + c0;
            const float* rrow = (EPI == 1 || EPI == 3) ? (res + (size_t)m * N + n0 + c0) : nullptr;
#pragma unroll
            for (int j = 0; j < 8; ++j) {
                float v = acc[i][j];
                if (EPI == 2) {
                    v += bias[n0 + c0 + j];
                    v = 0.5f * v * (1.0f + erff(v * 0.70710678118f));
                } else if (EPI == 1) {
                    v += rrow[j];
                } else if (EPI == 3) {
                    v += bias[n0 + c0 + j] + rrow[j];
                }
                crow[j] = v;
            }
        }
    }
}

// ---------------- flash attention (fp32) ----------------
// block: 128 query rows of one (b,h); iterate 128-key tiles; 256 threads
#define ANQ 128
#define ANK 128
#define PSTRIDE 132
#define FLASH_SMEM_FLOATS (64*128 + 64*128 + 128*64 + 128*PSTRIDE + 128 + 128)

__global__ __launch_bounds__(256, 1) void flash_kernel(
    const float* __restrict__ Qg_, const float* __restrict__ Kg_,
    const float* __restrict__ Vg_, float* __restrict__ O)
{
    extern __shared__ float sm[];
    float* Qs  = sm;                   // [64][128]  Q^T
    float* Ks  = sm + 64*128;          // [64][128]  K^T
    float* Vs  = Ks + 64*128;          // [128][64]
    float* Ps  = Vs + 128*64;          // [128][PSTRIDE] row-major
    float* rsc = Ps + 128*PSTRIDE;     // [128] per-row rescale
    float* rl  = rsc + 128;            // [128] per-row l

    const int tid = threadIdx.x;
    const int bh  = blockIdx.y;
    const int qt  = blockIdx.x;

    const float* Qg = Qg_ + (size_t)bh * NSEQ * DH + (size_t)qt * ANQ * DH;
    const float* Kbase = Kg_ + (size_t)bh * NSEQ * DH;
    const float* Vbase = Vg_ + (size_t)bh * NSEQ * DH;

    // load Q transposed
#pragma unroll
    for (int it = 0; it < 8; ++it) {
        int f  = tid + it * 256;      // float4 index 0..2047
        int r  = f >> 4;
        int d4 = (f & 15) * 4;
        float4 v = *(const float4*)(Qg + r * DH + d4);
        Qs[(d4+0)*128 + r] = v.x;
        Qs[(d4+1)*128 + r] = v.y;
        Qs[(d4+2)*128 + r] = v.z;
        Qs[(d4+3)*128 + r] = v.w;
    }

    const int r0 = (tid >> 4) * 8;    // score rows
    const int ck = (tid & 15) * 8;    // score cols (keys)
    const int pr = (tid >> 3) * 4;    // pv rows
    const int pd = (tid & 7) * 8;     // pv dims

    float m_i[8], l_i[8];
#pragma unroll
    for (int i = 0; i < 8; ++i) { m_i[i] = -1e30f; l_i[i] = 0.f; }
    float acc[4][8];
#pragma unroll
    for (int i = 0; i < 4; ++i)
#pragma unroll
        for (int j = 0; j < 8; ++j) acc[i][j] = 0.f;

    for (int kt = 0; kt < NSEQ / ANK; ++kt) {
        const float* Kt = Kbase + (size_t)kt * ANK * DH;
        const float* Vt = Vbase + (size_t)kt * ANK * DH;
#pragma unroll
        for (int it = 0; it < 8; ++it) {
            int f  = tid + it * 256;
            int r  = f >> 4;
            int d4 = (f & 15) * 4;
            float4 kv = *(const float4*)(Kt + r * DH + d4);
            Ks[(d4+0)*128 + r] = kv.x;
            Ks[(d4+1)*128 + r] = kv.y;
            Ks[(d4+2)*128 + r] = kv.z;
            Ks[(d4+3)*128 + r] = kv.w;
            *(float4*)(Vs + r * DH + d4) = *(const float4*)(Vt + r * DH + d4);
        }
        __syncthreads();

        // scores s = Q K^T
        float s[8][8];
#pragma unroll
        for (int i = 0; i < 8; ++i)
#pragma unroll
            for (int j = 0; j < 8; ++j) s[i][j] = 0.f;

#pragma unroll 4
        for (int d = 0; d < DH; ++d) {
            float4 a0 = *(const float4*)(Qs + d*128 + r0);
            float4 a1 = *(const float4*)(Qs + d*128 + r0 + 4);
            float4 b0 = *(const float4*)(Ks + d*128 + ck);
            float4 b1 = *(const float4*)(Ks + d*128 + ck + 4);
            float ar[8] = {a0.x,a0.y,a0.z,a0.w,a1.x,a1.y,a1.z,a1.w};
            float br[8] = {b0.x,b0.y,b0.z,b0.w,b1.x,b1.y,b1.z,b1.w};
#pragma unroll
            for (int i = 0; i < 8; ++i)
#pragma unroll
                for (int j = 0; j < 8; ++j)
                    s[i][j] = fmaf(ar[i], br[j], s[i][j]);
        }

        // online softmax per row
#pragma unroll
        for (int i = 0; i < 8; ++i) {
            float mx = -1e30f;
#pragma unroll
            for (int j = 0; j < 8; ++j) { s[i][j] *= 0.125f; mx = fmaxf(mx, s[i][j]); }
            mx = fmaxf(mx, __shfl_xor_sync(0xffffffffu, mx, 1, 16));
            mx = fmaxf(mx, __shfl_xor_sync(0xffffffffu, mx, 2, 16));
            mx = fmaxf(mx, __shfl_xor_sync(0xffffffffu, mx, 4, 16));
            mx = fmaxf(mx, __shfl_xor_sync(0xffffffffu, mx, 8, 16));
            float mnew = fmaxf(m_i[i], mx);
            float corr = __expf(m_i[i] - mnew);
            m_i[i] = mnew;
            float sum = 0.f;
#pragma unroll
            for (int j = 0; j < 8; ++j) { float p = __expf(s[i][j] - mnew); s[i][j] = p; sum += p; }
            sum += __shfl_xor_sync(0xffffffffu, sum, 1, 16);
            sum += __shfl_xor_sync(0xffffffffu, sum, 2, 16);
            sum += __shfl_xor_sync(0xffffffffu, sum, 4, 16);
            sum += __shfl_xor_sync(0xffffffffu, sum, 8, 16);
            l_i[i] = l_i[i] * corr + sum;
            if ((tid & 15) == 0) rsc[r0 + i] = corr;
            *(float4*)(Ps + (r0+i)*PSTRIDE + ck)     = make_float4(s[i][0], s[i][1], s[i][2], s[i][3]);
            *(float4*)(Ps + (r0+i)*PSTRIDE + ck + 4) = make_float4(s[i][4], s[i][5], s[i][6], s[i][7]);
        }
        __syncthreads();

        // rescale acc and accumulate P @ V
#pragma unroll
        for (int i = 0; i < 4; ++i) {
            float c = rsc[pr + i];
#pragma unroll
            for (int j = 0; j < 8; ++j) acc[i][j] *= c;
        }
#pragma unroll 4
        for (int kkk = 0; kkk < ANK; ++kkk) {
            float p0 = Ps[(pr+0)*PSTRIDE + kkk];
            float p1 = Ps[(pr+1)*PSTRIDE + kkk];
            float p2 = Ps[(pr+2)*PSTRIDE + kkk];
            float p3 = Ps[(pr+3)*PSTRIDE + kkk];
            float4 v0 = *(const float4*)(Vs + kkk*DH + pd);
            float4 v1 = *(const float4*)(Vs + kkk*DH + pd + 4);
            float vr[8] = {v0.x,v0.y,v0.z,v0.w,v1.x,v1.y,v1.z,v1.w};
#pragma unroll
            for (int j = 0; j < 8; ++j) {
                acc[0][j] = fmaf(p0, vr[j], acc[0][j]);
                acc[1][j] = fmaf(p1, vr[j], acc[1][j]);
                acc[2][j] = fmaf(p2, vr[j], acc[2][j]);
                acc[3][j] = fmaf(p3, vr[j], acc[3][j]);
            }
        }
        __syncthreads();
    }

    if ((tid & 15) == 0) {
#pragma unroll
        for (int i = 0; i < 8; ++i) rl[r0 + i] = l_i[i];
    }
    __syncthreads();

    const int b = bh >> 2, h = bh & 3;
#pragma unroll
    for (int i = 0; i < 4; ++i) {
        int row = qt * ANQ + pr + i;
        float inv = 1.0f / rl[pr + i];
        float* dst = O + ((size_t)(b * NSEQ + row)) * CDIM + h * DH + pd;
        float4 o0 = make_float4(acc[i][0]*inv, acc[i][1]*inv, acc[i][2]*inv, acc[i][3]*inv);
        float4 o1 = make_float4(acc[i][4]*inv, acc[i][5]*inv, acc[i][6]*inv, acc[i][7]*inv);
        *(float4*)dst       = o0;
        *(float4*)(dst + 4) = o1;
    }
}

// ---------------- layernorm over C=256 ----------------
__global__ __launch_bounds__(256) void ln_kernel(
    const float* __restrict__ x, float* __restrict__ y,
    const float* __restrict__ g, const float* __restrict__ b)
{
    __shared__ float red[8];
    const int row = blockIdx.x;
    const int t = threadIdx.x;
    float v = x[(size_t)row * CDIM + t];

    float s = v;
#pragma unroll
    for (int o = 16; o > 0; o >>= 1) s += __shfl_xor_sync(0xffffffffu, s, o);
    if ((t & 31) == 0) red[t >> 5] = s;
    __syncthreads();
    float tot = 0.f;
#pragma unroll
    for (int w = 0; w < 8; ++w) tot += red[w];
    float mu = tot * (1.0f / 256.0f);
    float d = v - mu;
    __syncthreads();

    float q = d * d;
#pragma unroll
    for (int o = 16; o > 0; o >>= 1) q += __shfl_xor_sync(0xffffffffu, q, o);
    if ((t & 31) == 0) red[t >> 5] = q;
    __syncthreads();
    float vtot = 0.f;
#pragma unroll
    for (int w = 0; w < 8; ++w) vtot += red[w];
    float var = vtot * (1.0f / 256.0f);

    y[(size_t)row * CDIM + t] = d * rsqrtf(var + 1e-5f) * g[t] + b[t];
}

// ---------------- launch ----------------
extern "C" void kernel_launch(void* const* d_in, const int* in_sizes, int n_in,
                              void* d_out, int out_size) {
    (void)in_sizes; (void)n_in; (void)out_size;
    const float* x     = (const float*)d_in[0];
    const float* Wqkv  = (const float*)d_in[1];
    const float* Wproj = (const float*)d_in[2];
    const float* g1    = (const float*)d_in[3];
    const float* b1    = (const float*)d_in[4];
    const float* g2    = (const float*)d_in[5];
    const float* b2    = (const float*)d_in[6];
    const float* W1    = (const float*)d_in[7];
    const float* bf1   = (const float*)d_in[8];
    const float* W2    = (const float*)d_in[9];
    const float* bf2   = (const float*)d_in[10];
    float* out = (float*)d_out;

    float *qkv, *attn, *x1, *x2, *hbuf;
    cudaGetSymbolAddress((void**)&qkv,  g_qkv);
    cudaGetSymbolAddress((void**)&attn, g_attn);
    cudaGetSymbolAddress((void**)&x1,   g_x1);
    cudaGetSymbolAddress((void**)&x2,   g_x2);
    cudaGetSymbolAddress((void**)&hbuf, g_h);

    // 1. QKV GEMM + RoPE scatter
    sgemm_kernel<0><<<dim3(768/128, MROWS/128), 256>>>(x, Wqkv, qkv, MROWS, 768, CDIM, nullptr, nullptr);

    // 2. flash attention
    const int flash_smem = FLASH_SMEM_FLOATS * (int)sizeof(float);
    cudaFuncSetAttribute(flash_kernel, cudaFuncAttributeMaxDynamicSharedMemorySize, flash_smem);
    flash_kernel<<<dim3(NSEQ/ANQ, BATCH*NHEADS), 256, flash_smem>>>(qkv, qkv + QS, qkv + 2ull*QS, attn);

    // 3. proj + residual(x)
    sgemm_kernel<1><<<dim3(CDIM/128, MROWS/128), 256>>>(attn, Wproj, x1, MROWS, CDIM, CDIM, nullptr, x);

    // 4. LN1
    ln_kernel<<<MROWS, 256>>>(x1, x2, g1, b1);

    // 5. MLP1: gelu(x2 @ W1^T + bf1)
    sgemm_kernel<2><<<dim3(1024/128, MROWS/128), 256>>>(x2, W1, hbuf, MROWS, 1024, CDIM, bf1, nullptr);

    // 6. MLP2: x2 + h @ W2^T + bf2   (write into x1)
    sgemm_kernel<3><<<dim3(CDIM/128, MROWS/128), 256>>>(hbuf, W2, x1, MROWS, CDIM, 1024, bf2, x2);

    // 7. LN2 -> out
    ln_kernel<<<MROWS, 256>>>(x1, out, g2, b2);
}

// round 6
// speedup vs baseline: 2.5768x; 2.5768x over previous
#include <cuda_runtime.h>
#include <cuda_bf16.h>
#include <math.h>
#include <stdint.h>

// ---------------- problem constants ----------------
#define BATCH   4
#define NSEQ    2304          // 48*48
#define CDIM    256
#define NHEADS  4
#define DH      64
#define HIMG    48
#define WIMG    48
#define MROWS   (BATCH*NSEQ)           // 9216
#define QS      (BATCH*NHEADS*NSEQ*DH) // 2359296 per q/k/v

// ---------------- scratch ----------------
__device__ float g_qkv[3ull*QS];          // [sel][b*h][n][64]
__device__ float g_attn[(size_t)MROWS*CDIM];
__device__ float g_x1[(size_t)MROWS*CDIM];
__device__ float g_x2[(size_t)MROWS*CDIM];
__device__ float g_h[(size_t)MROWS*4*CDIM];

// ---------------- tf32 helpers ----------------
__device__ __forceinline__ uint32_t f2tf(float f) {
    uint32_t u; asm("cvt.rna.tf32.f32 %0, %1;" : "=r"(u) : "f"(f)); return u;
}
__device__ __forceinline__ void mma_tf32(float* d, const uint32_t* a, const uint32_t* b) {
    asm volatile(
        "mma.sync.aligned.m16n8k8.row.col.f32.tf32.tf32.f32 "
        "{%0,%1,%2,%3}, {%4,%5,%6,%7}, {%8,%9}, {%0,%1,%2,%3};\n"
        : "+f"(d[0]), "+f"(d[1]), "+f"(d[2]), "+f"(d[3])
        : "r"(a[0]), "r"(a[1]), "r"(a[2]), "r"(a[3]), "r"(b[0]), "r"(b[1]));
}

// ---------------- TF32 tensor-core GEMM: C = A(MxK) * B(NxK)^T ----------------
// EPI 0: qkv + rope scatter | 1: +res | 2: +bias, gelu | 3: +bias +res
#define KT   32
#define APAD 36

template<int EPI>
__global__ __launch_bounds__(256) void tgemm_kernel(
    const float* __restrict__ A, const float* __restrict__ B, float* __restrict__ C,
    int M, int N, int K,
    const float* __restrict__ bias, const float* __restrict__ res)
{
    __shared__ uint32_t As[128*APAD];
    __shared__ uint32_t Bs[128*APAD];

    const int tid  = threadIdx.x;
    const int warp = tid >> 5;
    const int lane = tid & 31;
    const int m0 = blockIdx.y * 128;
    const int n0 = blockIdx.x * 128;
    const int warp_m = (warp & 3) * 32;
    const int warp_n = (warp >> 2) * 64;
    const int lg = lane >> 2;   // group id 0..7
    const int lt = lane & 3;    // thread in group

    // global load mapping: row = tid>>1, 16 floats at (tid&1)*16
    const int lrow = tid >> 1;
    const int lko  = (tid & 1) * 16;
    const float* Ap = A + (size_t)(m0 + lrow) * K + lko;
    const float* Bp = B + (size_t)(n0 + lrow) * K + lko;

    float4 ra[4], rb[4];
#pragma unroll
    for (int i = 0; i < 4; ++i) {
        ra[i] = *(const float4*)(Ap + i*4);
        rb[i] = *(const float4*)(Bp + i*4);
    }

    float acc[2][8][4];
#pragma unroll
    for (int mt = 0; mt < 2; ++mt)
#pragma unroll
        for (int nt = 0; nt < 8; ++nt)
#pragma unroll
            for (int e = 0; e < 4; ++e) acc[mt][nt][e] = 0.f;

    int kk = 0;
    for (;;) {
#pragma unroll
        for (int i = 0; i < 4; ++i) {
            uint4 ua = make_uint4(f2tf(ra[i].x), f2tf(ra[i].y), f2tf(ra[i].z), f2tf(ra[i].w));
            uint4 ub = make_uint4(f2tf(rb[i].x), f2tf(rb[i].y), f2tf(rb[i].z), f2tf(rb[i].w));
            *(uint4*)(&As[lrow*APAD + lko + i*4]) = ua;
            *(uint4*)(&Bs[lrow*APAD + lko + i*4]) = ub;
        }
        __syncthreads();

        kk += KT;
        const bool more = (kk < K);
        if (more) {
#pragma unroll
            for (int i = 0; i < 4; ++i) {
                ra[i] = *(const float4*)(Ap + kk + i*4);
                rb[i] = *(const float4*)(Bp + kk + i*4);
            }
        }

#pragma unroll
        for (int ks = 0; ks < KT; ks += 8) {
            uint32_t af[2][4];
#pragma unroll
            for (int mt = 0; mt < 2; ++mt) {
                int r = warp_m + mt*16 + lg;
                af[mt][0] = As[r*APAD + ks + lt];
                af[mt][1] = As[(r+8)*APAD + ks + lt];
                af[mt][2] = As[r*APAD + ks + 4 + lt];
                af[mt][3] = As[(r+8)*APAD + ks + 4 + lt];
            }
#pragma unroll
            for (int nt = 0; nt < 8; ++nt) {
                uint32_t bf[2];
                int rn = warp_n + nt*8 + lg;
                bf[0] = Bs[rn*APAD + ks + lt];
                bf[1] = Bs[rn*APAD + ks + 4 + lt];
#pragma unroll
                for (int mt = 0; mt < 2; ++mt)
                    mma_tf32(acc[mt][nt], af[mt], bf);
            }
        }
        if (!more) break;
        __syncthreads();
    }

    // ---------------- epilogue ----------------
#pragma unroll
    for (int mt = 0; mt < 2; ++mt) {
#pragma unroll
        for (int half = 0; half < 2; ++half) {
            int m = m0 + warp_m + mt*16 + lg + half*8;
            if (EPI == 0) {
                int b   = m / NSEQ;
                int pos = m - b * NSEQ;
                int yy  = pos / WIMG;
                int xx  = pos - yy * WIMG;
#pragma unroll
                for (int nt = 0; nt < 8; ++nt) {
                    int c = n0 + warp_n + nt*8 + 2*lt;       // even
                    float v0 = acc[mt][nt][2*half];
                    float v1 = acc[mt][nt][2*half + 1];
                    int sel = c >> 8;
                    int rem = c & 255;
                    int h = rem >> 6;
                    int d = rem & 63;
                    if (sel < 2) {
                        float coord = (d < 32) ? (float)yy : (float)xx;
                        int j0 = d & 31;
                        float f0 = exp2f(-(float)j0 * 0.41524101186f);
                        float f1 = exp2f(-(float)(j0 + 1) * 0.41524101186f);
                        float s0, cv0, s1, cv1;
                        sincosf(coord * f0, &s0, &cv0);
                        sincosf(coord * f1, &s1, &cv1);
                        float w0 = v0 * cv0 - v1 * s0;
                        float w1 = v1 * cv1 + v0 * s1;
                        v0 = w0; v1 = w1;
                    }
                    size_t base = (size_t)sel * QS +
                                  ((size_t)(b * NHEADS + h) * NSEQ + pos) * DH + d;
                    *(float2*)(C + base) = make_float2(v0, v1);
                }
            } else {
#pragma unroll
                for (int nt = 0; nt < 8; ++nt) {
                    int n = n0 + warp_n + nt*8 + 2*lt;
                    float v0 = acc[mt][nt][2*half];
                    float v1 = acc[mt][nt][2*half + 1];
                    if (EPI == 2) {
                        v0 += bias[n];   v1 += bias[n+1];
                        v0 = 0.5f * v0 * (1.0f + erff(v0 * 0.70710678118f));
                        v1 = 0.5f * v1 * (1.0f + erff(v1 * 0.70710678118f));
                    } else if (EPI == 1) {
                        float2 r2 = *(const float2*)(res + (size_t)m * N + n);
                        v0 += r2.x; v1 += r2.y;
                    } else if (EPI == 3) {
                        float2 r2 = *(const float2*)(res + (size_t)m * N + n);
                        v0 += bias[n]   + r2.x;
                        v1 += bias[n+1] + r2.y;
                    }
                    *(float2*)(C + (size_t)m * N + n) = make_float2(v0, v1);
                }
            }
        }
    }
}

// ---------------- TF32 flash attention ----------------
// 128 queries x one (b,h) per block; 128-key tiles; 8 warps, each warp owns
// 16 full query rows (all 128 key columns) -> warp-local softmax state.
#define DPAD 68
#define PPAD 132
#define FL_SMEM_U32 (3*128*DPAD + 128*PPAD)   // 43008 u32 = 172032 B

__global__ __launch_bounds__(256, 1) void flash_tf32_kernel(
    const float* __restrict__ Qg_, const float* __restrict__ Kg_,
    const float* __restrict__ Vg_, float* __restrict__ O)
{
    extern __shared__ uint32_t sm[];
    uint32_t* Qs = sm;                    // [128][DPAD] tf32
    uint32_t* Ks = Qs + 128*DPAD;
    uint32_t* Vs = Ks + 128*DPAD;
    uint32_t* Ps = Vs + 128*DPAD;         // [128][PPAD] tf32

    const int tid  = threadIdx.x;
    const int warp = tid >> 5;
    const int lane = tid & 31;
    const int lg = lane >> 2;
    const int lt = lane & 3;
    const int warp_m = warp * 16;

    const int bh = blockIdx.y;
    const int qt = blockIdx.x;

    const float* Qg    = Qg_ + (size_t)bh * NSEQ * DH + (size_t)qt * 128 * DH;
    const float* Kbase = Kg_ + (size_t)bh * NSEQ * DH;
    const float* Vbase = Vg_ + (size_t)bh * NSEQ * DH;

    // load Q (scaled by 1/sqrt(dh)) into tf32 smem
#pragma unroll
    for (int it = 0; it < 8; ++it) {
        int f  = it * 256 + tid;      // float4 index
        int r  = f >> 4;
        int c4 = (f & 15) * 4;
        float4 v = *(const float4*)(Qg + r * DH + c4);
        uint4 u = make_uint4(f2tf(v.x * 0.125f), f2tf(v.y * 0.125f),
                             f2tf(v.z * 0.125f), f2tf(v.w * 0.125f));
        *(uint4*)(&Qs[r*DPAD + c4]) = u;
    }

    float m_i[2], l_i[2];
    m_i[0] = m_i[1] = -1e30f;
    l_i[0] = l_i[1] = 0.f;
    float oacc[8][4];
#pragma unroll
    for (int nt = 0; nt < 8; ++nt)
#pragma unroll
        for (int e = 0; e < 4; ++e) oacc[nt][e] = 0.f;

    for (int kt = 0; kt < NSEQ / 128; ++kt) {
        __syncthreads();   // prior S/PV reads of Ks/Vs done
        const float* Kt = Kbase + (size_t)kt * 128 * DH;
        const float* Vt = Vbase + (size_t)kt * 128 * DH;
#pragma unroll
        for (int it = 0; it < 8; ++it) {
            int f  = it * 256 + tid;
            int r  = f >> 4;
            int c4 = (f & 15) * 4;
            float4 kv = *(const float4*)(Kt + r * DH + c4);
            float4 vv = *(const float4*)(Vt + r * DH + c4);
            *(uint4*)(&Ks[r*DPAD + c4]) = make_uint4(f2tf(kv.x), f2tf(kv.y), f2tf(kv.z), f2tf(kv.w));
            *(uint4*)(&Vs[r*DPAD + c4]) = make_uint4(f2tf(vv.x), f2tf(vv.y), f2tf(vv.z), f2tf(vv.w));
        }
        __syncthreads();

        // S = (Q/8) K^T  — warp: 16 rows x 128 keys = 16 n-tiles
        float sacc[16][4];
#pragma unroll
        for (int nt = 0; nt < 16; ++nt)
#pragma unroll
            for (int e = 0; e < 4; ++e) sacc[nt][e] = 0.f;

#pragma unroll
        for (int ks = 0; ks < DH; ks += 8) {
            uint32_t af[4];
            int r = warp_m + lg;
            af[0] = Qs[r*DPAD + ks + lt];
            af[1] = Qs[(r+8)*DPAD + ks + lt];
            af[2] = Qs[r*DPAD + ks + 4 + lt];
            af[3] = Qs[(r+8)*DPAD + ks + 4 + lt];
#pragma unroll
            for (int nt = 0; nt < 16; ++nt) {
                uint32_t bf[2];
                int rn = nt*8 + lg;
                bf[0] = Ks[rn*DPAD + ks + lt];
                bf[1] = Ks[rn*DPAD + ks + 4 + lt];
                mma_tf32(sacc[nt], af, bf);
            }
        }

        // online softmax (fully warp-local: each warp owns full rows)
#pragma unroll
        for (int half = 0; half < 2; ++half) {
            int rloc = warp_m + lg + half*8;
            float mx = -1e30f;
#pragma unroll
            for (int nt = 0; nt < 16; ++nt) {
                mx = fmaxf(mx, sacc[nt][2*half]);
                mx = fmaxf(mx, sacc[nt][2*half + 1]);
            }
            mx = fmaxf(mx, __shfl_xor_sync(0xffffffffu, mx, 1));
            mx = fmaxf(mx, __shfl_xor_sync(0xffffffffu, mx, 2));
            float mnew = fmaxf(m_i[half], mx);
            float corr = __expf(m_i[half] - mnew);
            m_i[half] = mnew;
            float sum = 0.f;
#pragma unroll
            for (int nt = 0; nt < 16; ++nt) {
                float p0 = __expf(sacc[nt][2*half]     - mnew);
                float p1 = __expf(sacc[nt][2*half + 1] - mnew);
                sum += p0 + p1;
                Ps[rloc*PPAD + nt*8 + 2*lt]     = f2tf(p0);
                Ps[rloc*PPAD + nt*8 + 2*lt + 1] = f2tf(p1);
            }
            sum += __shfl_xor_sync(0xffffffffu, sum, 1);
            sum += __shfl_xor_sync(0xffffffffu, sum, 2);
            l_i[half] = l_i[half] * corr + sum;
#pragma unroll
            for (int nt = 0; nt < 8; ++nt) {
                oacc[nt][2*half]     *= corr;
                oacc[nt][2*half + 1] *= corr;
            }
        }
        __syncwarp();   // P rows of this warp visible to this warp

        // O += P V  — warp: same 16 rows x 64 dims = 8 n-tiles, k over 128 keys
#pragma unroll
        for (int ks = 0; ks < 128; ks += 8) {
            uint32_t af[4];
            int r = warp_m + lg;
            af[0] = Ps[r*PPAD + ks + lt];
            af[1] = Ps[(r+8)*PPAD + ks + lt];
            af[2] = Ps[r*PPAD + ks + 4 + lt];
            af[3] = Ps[(r+8)*PPAD + ks + 4 + lt];
#pragma unroll
            for (int nt = 0; nt < 8; ++nt) {
                uint32_t bf[2];
                bf[0] = Vs[(ks + lt)*DPAD + nt*8 + lg];
                bf[1] = Vs[(ks + 4 + lt)*DPAD + nt*8 + lg];
                mma_tf32(oacc[nt], af, bf);
            }
        }
    }

    // write O / l
    const int b = bh >> 2, h = bh & 3;
#pragma unroll
    for (int half = 0; half < 2; ++half) {
        int row = qt * 128 + warp_m + lg + half*8;
        float inv = 1.0f / l_i[half];
        float* dst = O + ((size_t)(b * NSEQ + row)) * CDIM + h * DH;
#pragma unroll
        for (int nt = 0; nt < 8; ++nt) {
            float2 v = make_float2(oacc[nt][2*half] * inv, oacc[nt][2*half + 1] * inv);
            *(float2*)(dst + nt*8 + 2*lt) = v;
        }
    }
}

// ---------------- layernorm over C=256 ----------------
__global__ __launch_bounds__(256) void ln_kernel(
    const float* __restrict__ x, float* __restrict__ y,
    const float* __restrict__ g, const float* __restrict__ b)
{
    __shared__ float red[8];
    const int row = blockIdx.x;
    const int t = threadIdx.x;
    float v = x[(size_t)row * CDIM + t];

    float s = v;
#pragma unroll
    for (int o = 16; o > 0; o >>= 1) s += __shfl_xor_sync(0xffffffffu, s, o);
    if ((t & 31) == 0) red[t >> 5] = s;
    __syncthreads();
    float tot = 0.f;
#pragma unroll
    for (int w = 0; w < 8; ++w) tot += red[w];
    float mu = tot * (1.0f / 256.0f);
    float d = v - mu;
    __syncthreads();

    float q = d * d;
#pragma unroll
    for (int o = 16; o > 0; o >>= 1) q += __shfl_xor_sync(0xffffffffu, q, o);
    if ((t & 31) == 0) red[t >> 5] = q;
    __syncthreads();
    float vtot = 0.f;
#pragma unroll
    for (int w = 0; w < 8; ++w) vtot += red[w];
    float var = vtot * (1.0f / 256.0f);

    y[(size_t)row * CDIM + t] = d * rsqrtf(var + 1e-5f) * g[t] + b[t];
}

// ---------------- launch ----------------
extern "C" void kernel_launch(void* const* d_in, const int* in_sizes, int n_in,
                              void* d_out, int out_size) {
    (void)in_sizes; (void)n_in; (void)out_size;
    const float* x     = (const float*)d_in[0];
    const float* Wqkv  = (const float*)d_in[1];
    const float* Wproj = (const float*)d_in[2];
    const float* g1    = (const float*)d_in[3];
    const float* b1    = (const float*)d_in[4];
    const float* g2    = (const float*)d_in[5];
    const float* b2    = (const float*)d_in[6];
    const float* W1    = (const float*)d_in[7];
    const float* bf1   = (const float*)d_in[8];
    const float* W2    = (const float*)d_in[9];
    const float* bf2   = (const float*)d_in[10];
    float* out = (float*)d_out;

    float *qkv, *attn, *x1, *x2, *hbuf;
    cudaGetSymbolAddress((void**)&qkv,  g_qkv);
    cudaGetSymbolAddress((void**)&attn, g_attn);
    cudaGetSymbolAddress((void**)&x1,   g_x1);
    cudaGetSymbolAddress((void**)&x2,   g_x2);
    cudaGetSymbolAddress((void**)&hbuf, g_h);

    // 1. QKV GEMM + RoPE scatter
    tgemm_kernel<0><<<dim3(768/128, MROWS/128), 256>>>(x, Wqkv, qkv, MROWS, 768, CDIM, nullptr, nullptr);

    // 2. flash attention (tf32 tensor cores)
    const int flash_smem = FL_SMEM_U32 * (int)sizeof(uint32_t);
    cudaFuncSetAttribute(flash_tf32_kernel, cudaFuncAttributeMaxDynamicSharedMemorySize, flash_smem);
    flash_tf32_kernel<<<dim3(NSEQ/128, BATCH*NHEADS), 256, flash_smem>>>(qkv, qkv + QS, qkv + 2ull*QS, attn);

    // 3. proj + residual(x)
    tgemm_kernel<1><<<dim3(CDIM/128, MROWS/128), 256>>>(attn, Wproj, x1, MROWS, CDIM, CDIM, nullptr, x);

    // 4. LN1
    ln_kernel<<<MROWS, 256>>>(x1, x2, g1, b1);

    // 5. MLP1: gelu(x2 @ W1^T + bf1)
    tgemm_kernel<2><<<dim3(1024/128, MROWS/128), 256>>>(x2, W1, hbuf, MROWS, 1024, CDIM, bf1, nullptr);

    // 6. MLP2: x2 + h @ W2^T + bf2
    tgemm_kernel<3><<<dim3(CDIM/128, MROWS/128), 256>>>(hbuf, W2, x1, MROWS, CDIM, 1024, bf2, x2);

    // 7. LN2 -> out
    ln_kernel<<<MROWS, 256>>>(x1, out, g2, b2);
}

// round 8
// speedup vs baseline: 2.6185x; 1.0162x over previous
#include <cuda_runtime.h>
#include <cuda_bf16.h>
#include <math.h>
#include <stdint.h>

// ---------------- problem constants ----------------
#define BATCH   4
#define NSEQ    2304          // 48*48
#define CDIM    256
#define NHEADS  4
#define DH      64
#define WIMG    48
#define MROWS   (BATCH*NSEQ)           // 9216
#define QS      (BATCH*NHEADS*NSEQ*DH) // 2359296 per q/k/v

// ---------------- scratch ----------------
__device__ uint16_t g_qkv[3ull*QS];       // bf16 [sel][b*h][n][64]
__device__ float g_attn[(size_t)MROWS*CDIM];
__device__ float g_x1[(size_t)MROWS*CDIM];
__device__ float g_x2[(size_t)MROWS*CDIM];
__device__ float g_h[(size_t)MROWS*4*CDIM];

// ---------------- bf16 / mma helpers ----------------
__device__ __forceinline__ uint32_t pack_bf(float a, float b) {
    __nv_bfloat162 h = __floats2bfloat162_rn(a, b);
    return *reinterpret_cast<uint32_t*>(&h);
}
__device__ __forceinline__ void ldsm4(uint32_t* r, uint32_t addr) {
    asm volatile("ldmatrix.sync.aligned.m8n8.x4.shared.b16 {%0,%1,%2,%3}, [%4];"
        : "=r"(r[0]), "=r"(r[1]), "=r"(r[2]), "=r"(r[3]) : "r"(addr));
}
__device__ __forceinline__ void ldsm4t(uint32_t* r, uint32_t addr) {
    asm volatile("ldmatrix.sync.aligned.m8n8.x4.trans.shared.b16 {%0,%1,%2,%3}, [%4];"
        : "=r"(r[0]), "=r"(r[1]), "=r"(r[2]), "=r"(r[3]) : "r"(addr));
}
__device__ __forceinline__ void mma_bf16(float* d, const uint32_t* a, const uint32_t* b) {
    asm volatile(
        "mma.sync.aligned.m16n8k16.row.col.f32.bf16.bf16.f32 "
        "{%0,%1,%2,%3}, {%4,%5,%6,%7}, {%8,%9}, {%0,%1,%2,%3};\n"
        : "+f"(d[0]), "+f"(d[1]), "+f"(d[2]), "+f"(d[3])
        : "r"(a[0]), "r"(a[1]), "r"(a[2]), "r"(a[3]), "r"(b[0]), "r"(b[1]));
}

// ---------------- bf16 tensor-core GEMM: C = A(MxK) * B(NxK)^T ----------------
// EPI 0: qkv + rope -> bf16 scatter | 1: +res | 2: +bias, gelu | 3: +bias +res
#define BK  32
#define PIT 40     // bf16 elems per smem row (80B -> conflict-free LDSM)

template<int EPI>
__global__ __launch_bounds__(256) void bgemm_kernel(
    const float* __restrict__ A, const float* __restrict__ B, void* __restrict__ Cv,
    int M, int N, int K,
    const float* __restrict__ bias, const float* __restrict__ res)
{
    __shared__ alignas(16) uint16_t As[128*PIT];
    __shared__ alignas(16) uint16_t Bs[128*PIT];

    const int tid  = threadIdx.x;
    const int warp = tid >> 5;
    const int lane = tid & 31;
    const int m0 = blockIdx.y * 128;
    const int n0 = blockIdx.x * 128;
    const int warp_m = (warp & 3) * 32;
    const int warp_n = (warp >> 2) * 64;
    const int lg = lane >> 2;
    const int lt = lane & 3;

    const int lrow = tid >> 1;
    const int lko  = (tid & 1) * 16;
    const float* Ap = A + (size_t)(m0 + lrow) * K + lko;
    const float* Bp = B + (size_t)(n0 + lrow) * K + lko;

    const uint32_t asBase = (uint32_t)__cvta_generic_to_shared(As);
    const uint32_t bsBase = (uint32_t)__cvta_generic_to_shared(Bs);

    // ldmatrix per-lane element offsets (x2 for bytes at use site)
    const int aRow = (lane & 15);
    const int aCol = (lane >> 4) * 8;
    const int bRow = (lane >> 4) * 8 + (lane & 7);
    const int bCol = ((lane >> 3) & 1) * 8;

    float4 ra[4], rb[4];
#pragma unroll
    for (int i = 0; i < 4; ++i) { ra[i] = *(const float4*)(Ap + i*4); rb[i] = *(const float4*)(Bp + i*4); }

    float acc[2][8][4];
#pragma unroll
    for (int mt = 0; mt < 2; ++mt)
#pragma unroll
        for (int nt = 0; nt < 8; ++nt)
#pragma unroll
            for (int e = 0; e < 4; ++e) acc[mt][nt][e] = 0.f;

    int kk = 0;
    for (;;) {
        uint32_t ua[8], ub[8];
#pragma unroll
        for (int i = 0; i < 4; ++i) {
            ua[2*i]   = pack_bf(ra[i].x, ra[i].y);
            ua[2*i+1] = pack_bf(ra[i].z, ra[i].w);
            ub[2*i]   = pack_bf(rb[i].x, rb[i].y);
            ub[2*i+1] = pack_bf(rb[i].z, rb[i].w);
        }
        *(uint4*)(&As[lrow*PIT + lko])     = make_uint4(ua[0], ua[1], ua[2], ua[3]);
        *(uint4*)(&As[lrow*PIT + lko + 8]) = make_uint4(ua[4], ua[5], ua[6], ua[7]);
        *(uint4*)(&Bs[lrow*PIT + lko])     = make_uint4(ub[0], ub[1], ub[2], ub[3]);
        *(uint4*)(&Bs[lrow*PIT + lko + 8]) = make_uint4(ub[4], ub[5], ub[6], ub[7]);
        __syncthreads();

        kk += BK;
        const bool more = (kk < K);
        if (more) {
#pragma unroll
            for (int i = 0; i < 4; ++i) {
                ra[i] = *(const float4*)(Ap + kk + i*4);
                rb[i] = *(const float4*)(Bp + kk + i*4);
            }
        }

#pragma unroll
        for (int ks = 0; ks < BK; ks += 16) {
            uint32_t af[2][4];
#pragma unroll
            for (int mt = 0; mt < 2; ++mt)
                ldsm4(af[mt], asBase + 2*((warp_m + mt*16 + aRow)*PIT + ks + aCol));
#pragma unroll
            for (int np = 0; np < 4; ++np) {
                uint32_t bf[4];
                ldsm4(bf, bsBase + 2*((warp_n + np*16 + bRow)*PIT + ks + bCol));
#pragma unroll
                for (int mt = 0; mt < 2; ++mt) {
                    mma_bf16(acc[mt][np*2],     af[mt], bf);
                    mma_bf16(acc[mt][np*2 + 1], af[mt], bf + 2);
                }
            }
        }
        if (!more) break;
        __syncthreads();
    }

    // ---------------- epilogue ----------------
#pragma unroll
    for (int mt = 0; mt < 2; ++mt) {
#pragma unroll
        for (int half = 0; half < 2; ++half) {
            int m = m0 + warp_m + mt*16 + lg + half*8;
            if (EPI == 0) {
                uint16_t* C = (uint16_t*)Cv;
                int b   = m / NSEQ;
                int pos = m - b * NSEQ;
                int yy  = pos / WIMG;
                int xx  = pos - yy * WIMG;
#pragma unroll
                for (int nt = 0; nt < 8; ++nt) {
                    int c = n0 + warp_n + nt*8 + 2*lt;
                    float v0 = acc[mt][nt][2*half];
                    float v1 = acc[mt][nt][2*half + 1];
                    int sel = c >> 8;
                    int rem = c & 255;
                    int h = rem >> 6;
                    int d = rem & 63;
                    if (sel < 2) {
                        float coord = (d < 32) ? (float)yy : (float)xx;
                        int j0 = d & 31;
                        float f0 = exp2f(-(float)j0 * 0.41524101186f);
                        float f1 = exp2f(-(float)(j0 + 1) * 0.41524101186f);
                        float s0, cv0, s1, cv1;
                        sincosf(coord * f0, &s0, &cv0);
                        sincosf(coord * f1, &s1, &cv1);
                        float w0 = v0 * cv0 - v1 * s0;
                        float w1 = v1 * cv1 + v0 * s1;
                        v0 = w0; v1 = w1;
                    }
                    size_t base = (size_t)sel * QS +
                                  ((size_t)(b * NHEADS + h) * NSEQ + pos) * DH + d;
                    *(uint32_t*)(C + base) = pack_bf(v0, v1);
                }
            } else {
                float* C = (float*)Cv;
#pragma unroll
                for (int nt = 0; nt < 8; ++nt) {
                    int n = n0 + warp_n + nt*8 + 2*lt;
                    float v0 = acc[mt][nt][2*half];
                    float v1 = acc[mt][nt][2*half + 1];
                    if (EPI == 2) {
                        v0 += bias[n];   v1 += bias[n+1];
                        v0 = 0.5f * v0 * (1.0f + erff(v0 * 0.70710678118f));
                        v1 = 0.5f * v1 * (1.0f + erff(v1 * 0.70710678118f));
                    } else if (EPI == 1) {
                        float2 r2 = *(const float2*)(res + (size_t)m * N + n);
                        v0 += r2.x; v1 += r2.y;
                    } else if (EPI == 3) {
                        float2 r2 = *(const float2*)(res + (size_t)m * N + n);
                        v0 += bias[n]   + r2.x;
                        v1 += bias[n+1] + r2.y;
                    }
                    *(float2*)(C + (size_t)m * N + n) = make_float2(v0, v1);
                }
            }
        }
    }
}

// ---------------- bf16 flash attention ----------------
// 128 queries x one (b,h) per block; 128-key tiles; 8 warps, each warp owns
// 16 full query rows -> warp-local softmax state, ldmatrix + m16n8k16.
#define QPIT 72     // bf16 elems (144B rows, conflict-free LDSM)
#define PPIT 136    // bf16 elems (272B rows)
#define FL_SMEM_BYTES ((3*128*QPIT + 128*PPIT) * 2)   // 90112 B

__global__ __launch_bounds__(256, 1) void flash_bf16_kernel(
    const uint16_t* __restrict__ Qg_, const uint16_t* __restrict__ Kg_,
    const uint16_t* __restrict__ Vg_, float* __restrict__ O)
{
    extern __shared__ uint16_t smb[];
    uint16_t* Qs = smb;
    uint16_t* Ks = Qs + 128*QPIT;
    uint16_t* Vs = Ks + 128*QPIT;
    uint16_t* Ps = Vs + 128*QPIT;

    const int tid  = threadIdx.x;
    const int warp = tid >> 5;
    const int lane = tid & 31;
    const int lg = lane >> 2;
    const int lt = lane & 3;
    const int warp_m = warp * 16;

    const int bh = blockIdx.y;
    const int qt = blockIdx.x;

    const uint16_t* Qg    = Qg_ + (size_t)bh * NSEQ * DH + (size_t)qt * 128 * DH;
    const uint16_t* Kbase = Kg_ + (size_t)bh * NSEQ * DH;
    const uint16_t* Vbase = Vg_ + (size_t)bh * NSEQ * DH;

    const uint32_t qBase = (uint32_t)__cvta_generic_to_shared(Qs);
    const uint32_t kBase = (uint32_t)__cvta_generic_to_shared(Ks);
    const uint32_t vBase = (uint32_t)__cvta_generic_to_shared(Vs);
    const uint32_t pBase = (uint32_t)__cvta_generic_to_shared(Ps);

    const int aRow = (lane & 15);
    const int aCol = (lane >> 4) * 8;
    const int bRow = (lane >> 4) * 8 + (lane & 7);
    const int bCol = ((lane >> 3) & 1) * 8;
    const int tRow = ((lane >> 3) & 1) * 8 + (lane & 7);   // trans: key-row part
    const int tCol = (lane >> 4) * 8;                      // trans: d-col part

    // load Q tile (bf16, 128x64)
#pragma unroll
    for (int it = 0; it < 4; ++it) {
        int f  = it * 256 + tid;       // uint4 index (8 bf16 each)
        int r  = f >> 3;
        int c8 = (f & 7) * 8;
        *(uint4*)(&Qs[r*QPIT + c8]) = *(const uint4*)(Qg + r * DH + c8);
    }

    float m_i[2], l_i[2];
    m_i[0] = m_i[1] = -1e30f;
    l_i[0] = l_i[1] = 0.f;
    float oacc[8][4];
#pragma unroll
    for (int nt = 0; nt < 8; ++nt)
#pragma unroll
        for (int e = 0; e < 4; ++e) oacc[nt][e] = 0.f;

    for (int kt = 0; kt < NSEQ / 128; ++kt) {
        __syncthreads();
        const uint16_t* Kt = Kbase + (size_t)kt * 128 * DH;
        const uint16_t* Vt = Vbase + (size_t)kt * 128 * DH;
#pragma unroll
        for (int it = 0; it < 4; ++it) {
            int f  = it * 256 + tid;
            int r  = f >> 3;
            int c8 = (f & 7) * 8;
            *(uint4*)(&Ks[r*QPIT + c8]) = *(const uint4*)(Kt + r * DH + c8);
            *(uint4*)(&Vs[r*QPIT + c8]) = *(const uint4*)(Vt + r * DH + c8);
        }
        __syncthreads();

        // S = Q K^T : 16 rows x 128 keys
        float sacc[16][4];
#pragma unroll
        for (int nt = 0; nt < 16; ++nt)
#pragma unroll
            for (int e = 0; e < 4; ++e) sacc[nt][e] = 0.f;

#pragma unroll
        for (int ks = 0; ks < DH; ks += 16) {
            uint32_t af[4];
            ldsm4(af, qBase + 2*((warp_m + aRow)*QPIT + ks + aCol));
#pragma unroll
            for (int np = 0; np < 8; ++np) {
                uint32_t bf[4];
                ldsm4(bf, kBase + 2*((np*16 + bRow)*QPIT + ks + bCol));
                mma_bf16(sacc[np*2],     af, bf);
                mma_bf16(sacc[np*2 + 1], af, bf + 2);
            }
        }

        // online softmax (warp-local rows), scale 1/sqrt(64)=0.125 here
#pragma unroll
        for (int half = 0; half < 2; ++half) {
            int rloc = warp_m + lg + half*8;
            float mx = -1e30f;
#pragma unroll
            for (int nt = 0; nt < 16; ++nt) {
                sacc[nt][2*half]     *= 0.125f;
                sacc[nt][2*half + 1] *= 0.125f;
                mx = fmaxf(mx, sacc[nt][2*half]);
                mx = fmaxf(mx, sacc[nt][2*half + 1]);
            }
            mx = fmaxf(mx, __shfl_xor_sync(0xffffffffu, mx, 1));
            mx = fmaxf(mx, __shfl_xor_sync(0xffffffffu, mx, 2));
            float mnew = fmaxf(m_i[half], mx);
            float corr = __expf(m_i[half] - mnew);
            m_i[half] = mnew;
            float sum = 0.f;
#pragma unroll
            for (int nt = 0; nt < 16; ++nt) {
                float p0 = __expf(sacc[nt][2*half]     - mnew);
                float p1 = __expf(sacc[nt][2*half + 1] - mnew);
                sum += p0 + p1;
                *(uint32_t*)(&Ps[rloc*PPIT + nt*8 + 2*lt]) = pack_bf(p0, p1);
            }
            sum += __shfl_xor_sync(0xffffffffu, sum, 1);
            sum += __shfl_xor_sync(0xffffffffu, sum, 2);
            l_i[half] = l_i[half] * corr + sum;
#pragma unroll
            for (int nt = 0; nt < 8; ++nt) {
                oacc[nt][2*half]     *= corr;
                oacc[nt][2*half + 1] *= corr;
            }
        }
        __syncwarp();   // this warp's P rows visible to itself

        // O += P V : 16 rows x 64 dims, k over 128 keys
#pragma unroll
        for (int ks = 0; ks < 128; ks += 16) {
            uint32_t af[4];
            ldsm4(af, pBase + 2*((warp_m + aRow)*PPIT + ks + aCol));
#pragma unroll
            for (int np = 0; np < 4; ++np) {
                uint32_t bf[4];
                ldsm4t(bf, vBase + 2*((ks + tRow)*QPIT + np*16 + tCol));
                mma_bf16(oacc[np*2],     af, bf);
                mma_bf16(oacc[np*2 + 1], af, bf + 2);
            }
        }
    }

    // write O
    const int b = bh >> 2, h = bh & 3;
#pragma unroll
    for (int half = 0; half < 2; ++half) {
        int row = qt * 128 + warp_m + lg + half*8;
        float inv = 1.0f / l_i[half];
        float* dst = O + ((size_t)(b * NSEQ + row)) * CDIM + h * DH;
#pragma unroll
        for (int nt = 0; nt < 8; ++nt) {
            float2 v = make_float2(oacc[nt][2*half] * inv, oacc[nt][2*half + 1] * inv);
            *(float2*)(dst + nt*8 + 2*lt) = v;
        }
    }
}

// ---------------- layernorm over C=256: one warp per row ----------------
__global__ __launch_bounds__(256) void ln_kernel(
    const float* __restrict__ x, float* __restrict__ y,
    const float* __restrict__ g, const float* __restrict__ b)
{
    const int warp = threadIdx.x >> 5;
    const int lane = threadIdx.x & 31;
    const int row  = blockIdx.x * 8 + warp;

    const float4* xr = (const float4*)(x + (size_t)row * CDIM) + lane * 2;
    float4 a = xr[0], c = xr[1];

    float s = a.x + a.y + a.z + a.w + c.x + c.y + c.z + c.w;
#pragma unroll
    for (int o = 16; o > 0; o >>= 1) s += __shfl_xor_sync(0xffffffffu, s, o);
    float mu = s * (1.0f / 256.0f);

    float d0 = a.x - mu, d1 = a.y - mu, d2 = a.z - mu, d3 = a.w - mu;
    float d4 = c.x - mu, d5 = c.y - mu, d6 = c.z - mu, d7 = c.w - mu;
    float q = d0*d0 + d1*d1 + d2*d2 + d3*d3 + d4*d4 + d5*d5 + d6*d6 + d7*d7;
#pragma unroll
    for (int o = 16; o > 0; o >>= 1) q += __shfl_xor_sync(0xffffffffu, q, o);
    float r = rsqrtf(q * (1.0f / 256.0f) + 1e-5f);

    const float4* gp = (const float4*)g + lane * 2;
    const float4* bp = (const float4*)b + lane * 2;
    float4 g0 = gp[0], g1 = gp[1], b0 = bp[0], b1 = bp[1];

    float4* yr = (float4*)(y + (size_t)row * CDIM) + lane * 2;
    yr[0] = make_float4(d0*r*g0.x + b0.x, d1*r*g0.y + b0.y, d2*r*g0.z + b0.z, d3*r*g0.w + b0.w);
    yr[1] = make_float4(d4*r*g1.x + b1.x, d5*r*g1.y + b1.y, d6*r*g1.z + b1.z, d7*r*g1.w + b1.w);
}

// ---------------- launch ----------------
extern "C" void kernel_launch(void* const* d_in, const int* in_sizes, int n_in,
                              void* d_out, int out_size) {
    (void)in_sizes; (void)n_in; (void)out_size;
    const float* x     = (const float*)d_in[0];
    const float* Wqkv  = (const float*)d_in[1];
    const float* Wproj = (const float*)d_in[2];
    const float* g1    = (const float*)d_in[3];
    const float* b1    = (const float*)d_in[4];
    const float* g2    = (const float*)d_in[5];
    const float* b2    = (const float*)d_in[6];
    const float* W1    = (const float*)d_in[7];
    const float* bf1   = (const float*)d_in[8];
    const float* W2    = (const float*)d_in[9];
    const float* bf2   = (const float*)d_in[10];
    float* out = (float*)d_out;

    uint16_t* qkv;
    float *attn, *x1, *x2, *hbuf;
    cudaGetSymbolAddress((void**)&qkv,  g_qkv);
    cudaGetSymbolAddress((void**)&attn, g_attn);
    cudaGetSymbolAddress((void**)&x1,   g_x1);
    cudaGetSymbolAddress((void**)&x2,   g_x2);
    cudaGetSymbolAddress((void**)&hbuf, g_h);

    // 1. QKV GEMM + RoPE -> bf16 scatter
    bgemm_kernel<0><<<dim3(768/128, MROWS/128), 256>>>(x, Wqkv, qkv, MROWS, 768, CDIM, nullptr, nullptr);

    // 2. bf16 flash attention
    cudaFuncSetAttribute(flash_bf16_kernel, cudaFuncAttributeMaxDynamicSharedMemorySize, FL_SMEM_BYTES);
    flash_bf16_kernel<<<dim3(NSEQ/128, BATCH*NHEADS), 256, FL_SMEM_BYTES>>>(
        qkv, qkv + (size_t)QS, qkv + 2ull*QS, attn);

    // 3. proj + residual(x)
    bgemm_kernel<1><<<dim3(CDIM/128, MROWS/128), 256>>>(attn, Wproj, x1, MROWS, CDIM, CDIM, nullptr, x);

    // 4. LN1
    ln_kernel<<<MROWS/8, 256>>>(x1, x2, g1, b1);

    // 5. MLP1: gelu(x2 @ W1^T + bf1)
    bgemm_kernel<2><<<dim3(1024/128, MROWS/128), 256>>>(x2, W1, hbuf, MROWS, 1024, CDIM, bf1, nullptr);

    // 6. MLP2: x2 + h @ W2^T + bf2
    bgemm_kernel<3><<<dim3(CDIM/128, MROWS/128), 256>>>(hbuf, W2, x1, MROWS, CDIM, 1024, bf2, x2);

    // 7. LN2 -> out
    ln_kernel<<<MROWS/8, 256>>>(x1, out, g2, b2);
}

// round 11
// speedup vs baseline: 5.6197x; 2.1461x over previous
#include <cuda_runtime.h>
#include <cuda_bf16.h>
#include <math.h>
#include <stdint.h>

// ---------------- problem constants ----------------
#define BATCH   4
#define NSEQ    2304          // 48*48
#define CDIM    256
#define NHEADS  4
#define DH      64
#define WIMG    48
#define MROWS   (BATCH*NSEQ)           // 9216
#define QS      (BATCH*NHEADS*NSEQ*DH) // 2359296 per q/k/v

// bf16 weight-pool offsets
#define WQKV_E  196608
#define WPROJ_E 65536
#define W1_E    262144
#define W2_E    262144
#define WQKV_OFF  0
#define WPROJ_OFF (WQKV_E)
#define W1_OFF    (WQKV_E + WPROJ_E)
#define W2_OFF    (WQKV_E + WPROJ_E + W1_E)
#define WTOT_E    (WQKV_E + WPROJ_E + W1_E + W2_E)   // 786432
#define XE        ((size_t)MROWS*CDIM)               // 2359296

// ---------------- scratch ----------------
__device__ uint16_t g_qkv[3ull*QS];        // bf16 q/k/v [sel][b*h][n][64]
__device__ uint16_t g_xbf[XE];             // bf16 copy of x
__device__ uint16_t g_wbf[WTOT_E];         // bf16 weights
__device__ uint16_t g_attnbf[XE];          // bf16 attention output
__device__ uint16_t g_x2bf[XE];            // bf16 LN1 output
__device__ uint16_t g_hbf[(size_t)MROWS*4*CDIM];  // bf16 gelu output
__device__ float    g_x1[XE];              // f32
__device__ float    g_x2[XE];              // f32 LN1 output (residual)

// ---------------- helpers ----------------
__device__ __forceinline__ uint32_t pack_bf(float a, float b) {
    __nv_bfloat162 h = __floats2bfloat162_rn(a, b);
    return *reinterpret_cast<uint32_t*>(&h);
}
__device__ __forceinline__ void ldsm4(uint32_t* r, uint32_t addr) {
    asm volatile("ldmatrix.sync.aligned.m8n8.x4.shared.b16 {%0,%1,%2,%3}, [%4];"
        : "=r"(r[0]), "=r"(r[1]), "=r"(r[2]), "=r"(r[3]) : "r"(addr));
}
__device__ __forceinline__ void ldsm4t(uint32_t* r, uint32_t addr) {
    asm volatile("ldmatrix.sync.aligned.m8n8.x4.trans.shared.b16 {%0,%1,%2,%3}, [%4];"
        : "=r"(r[0]), "=r"(r[1]), "=r"(r[2]), "=r"(r[3]) : "r"(addr));
}
__device__ __forceinline__ void mma_bf16(float* d, const uint32_t* a, const uint32_t* b) {
    asm volatile(
        "mma.sync.aligned.m16n8k16.row.col.f32.bf16.bf16.f32 "
        "{%0,%1,%2,%3}, {%4,%5,%6,%7}, {%8,%9}, {%0,%1,%2,%3};\n"
        : "+f"(d[0]), "+f"(d[1]), "+f"(d[2]), "+f"(d[3])
        : "r"(a[0]), "r"(a[1]), "r"(a[2]), "r"(a[3]), "r"(b[0]), "r"(b[1]));
}
__device__ __forceinline__ void cp16(uint32_t smem, const void* g) {
    asm volatile("cp.async.cg.shared.global [%0], [%1], 16;" :: "r"(smem), "l"(g) : "memory");
}
__device__ __forceinline__ void cpcommit() { asm volatile("cp.async.commit_group;" ::: "memory"); }
template<int N> __device__ __forceinline__ void cpwait() {
    asm volatile("cp.async.wait_group %0;" :: "n"(N) : "memory");
}

// ---------------- f32 -> bf16 pre-convert (x + all weights) ----------------
__global__ __launch_bounds__(256) void cvt_kernel(
    const float* __restrict__ x, const float* __restrict__ wqkv,
    const float* __restrict__ wproj, const float* __restrict__ w1,
    const float* __restrict__ w2,
    uint16_t* __restrict__ xbf, uint16_t* __restrict__ wbf)
{
    size_t e = ((size_t)blockIdx.x * 256 + threadIdx.x) * 4;
    const float* src; uint16_t* dst;
    if (e < XE) { src = x + e; dst = xbf + e; }
    else {
        size_t r = e - XE;
        dst = wbf + r;
        if      (r < WPROJ_OFF) src = wqkv  + r;
        else if (r < W1_OFF)    src = wproj + (r - WPROJ_OFF);
        else if (r < W2_OFF)    src = w1    + (r - W1_OFF);
        else                    src = w2    + (r - W2_OFF);
    }
    float4 v = *(const float4*)src;
    *(uint2*)dst = make_uint2(pack_bf(v.x, v.y), pack_bf(v.z, v.w));
}

// ---------------- bf16 pipelined GEMM: C = A(MxK) * B(NxK)^T ----------------
// A,B bf16. EPI 0: rope->bf16 qkv scatter | 1: +res f32 | 2: +bias gelu -> bf16 | 3: +bias +res f32
#define BK   64
#define PIT  72                       // bf16 elems per smem row (144B)
#define STGB (128*PIT*2)              // stage bytes = 18432
#define GEMM_SMEM (4*STGB)            // A0,A1,B0,B1 = 73728B

template<int EPI>
__global__ __launch_bounds__(256) void bgemm_kernel(
    const uint16_t* __restrict__ A, const uint16_t* __restrict__ B, void* __restrict__ Cv,
    int M, int N, int K,
    const float* __restrict__ bias, const float* __restrict__ res)
{
    extern __shared__ uint16_t smg[];
    const uint32_t asBase = (uint32_t)__cvta_generic_to_shared(smg);
    const uint32_t bsBase = asBase + 2*STGB;

    const int tid  = threadIdx.x;
    const int warp = tid >> 5;
    const int lane = tid & 31;
    const int m0 = blockIdx.y * 128;
    const int n0 = blockIdx.x * 128;
    const int warp_m = (warp & 3) * 32;
    const int warp_n = (warp >> 2) * 64;
    const int lg = lane >> 2;
    const int lt = lane & 3;

    const int aRow = (lane & 15);
    const int aCol = (lane >> 4) * 8;
    const int bRow = (lane >> 4) * 8 + (lane & 7);
    const int bCol = ((lane >> 3) & 1) * 8;

    const uint16_t* Ap0 = A + (size_t)m0 * K;
    const uint16_t* Bp0 = B + (size_t)n0 * K;
    const int nT = K / BK;

    // issue one stage: 128 rows x 64 bf16 per operand, 16B chunks
    auto issue = [&](int t, int s) {
        const int k0 = t * BK;
#pragma unroll
        for (int it = 0; it < 4; ++it) {
            int c   = it * 256 + tid;
            int row = c >> 3;
            int ce  = (c & 7) * 8;
            cp16(asBase + s*STGB + 2*(row*PIT + ce), Ap0 + (size_t)row*K + k0 + ce);
            cp16(bsBase + s*STGB + 2*(row*PIT + ce), Bp0 + (size_t)row*K + k0 + ce);
        }
    };

    float acc[2][8][4];
#pragma unroll
    for (int mt = 0; mt < 2; ++mt)
#pragma unroll
        for (int nt = 0; nt < 8; ++nt)
#pragma unroll
            for (int e = 0; e < 4; ++e) acc[mt][nt][e] = 0.f;

    issue(0, 0); cpcommit();
    issue(1, 1); cpcommit();

    for (int t = 0; t < nT; ++t) {
        const int s = t & 1;
        cpwait<1>();
        __syncthreads();

#pragma unroll
        for (int ks = 0; ks < BK; ks += 16) {
            uint32_t af[2][4];
#pragma unroll
            for (int mt = 0; mt < 2; ++mt)
                ldsm4(af[mt], asBase + s*STGB + 2*((warp_m + mt*16 + aRow)*PIT + ks + aCol));
#pragma unroll
            for (int np = 0; np < 4; ++np) {
                uint32_t bf[4];
                ldsm4(bf, bsBase + s*STGB + 2*((warp_n + np*16 + bRow)*PIT + ks + bCol));
#pragma unroll
                for (int mt = 0; mt < 2; ++mt) {
                    mma_bf16(acc[mt][np*2],     af[mt], bf);
                    mma_bf16(acc[mt][np*2 + 1], af[mt], bf + 2);
                }
            }
        }
        __syncthreads();
        if (t + 2 < nT) issue(t + 2, s);
        cpcommit();
    }

    // ---------------- epilogue ----------------
#pragma unroll
    for (int mt = 0; mt < 2; ++mt) {
#pragma unroll
        for (int half = 0; half < 2; ++half) {
            int m = m0 + warp_m + mt*16 + lg + half*8;
            if (EPI == 0) {
                uint16_t* C = (uint16_t*)Cv;
                int b   = m / NSEQ;
                int pos = m - b * NSEQ;
                int yy  = pos / WIMG;
                int xx  = pos - yy * WIMG;
#pragma unroll
                for (int nt = 0; nt < 8; ++nt) {
                    int c = n0 + warp_n + nt*8 + 2*lt;
                    float v0 = acc[mt][nt][2*half];
                    float v1 = acc[mt][nt][2*half + 1];
                    int sel = c >> 8;
                    int rem = c & 255;
                    int h = rem >> 6;
                    int d = rem & 63;
                    if (sel < 2) {
                        float coord = (d < 32) ? (float)yy : (float)xx;
                        int j0 = d & 31;
                        float f0 = exp2f(-(float)j0 * 0.41524101186f);
                        float f1 = exp2f(-(float)(j0 + 1) * 0.41524101186f);
                        float s0, cv0, s1, cv1;
                        sincosf(coord * f0, &s0, &cv0);
                        sincosf(coord * f1, &s1, &cv1);
                        float w0 = v0 * cv0 - v1 * s0;
                        float w1 = v1 * cv1 + v0 * s1;
                        v0 = w0; v1 = w1;
                    }
                    size_t base = (size_t)sel * QS +
                                  ((size_t)(b * NHEADS + h) * NSEQ + pos) * DH + d;
                    *(uint32_t*)(C + base) = pack_bf(v0, v1);
                }
            } else if (EPI == 2) {
                uint16_t* C = (uint16_t*)Cv;
#pragma unroll
                for (int nt = 0; nt < 8; ++nt) {
                    int n = n0 + warp_n + nt*8 + 2*lt;
                    float v0 = acc[mt][nt][2*half] + bias[n];
                    float v1 = acc[mt][nt][2*half + 1] + bias[n+1];
                    v0 = 0.5f * v0 * (1.0f + erff(v0 * 0.70710678118f));
                    v1 = 0.5f * v1 * (1.0f + erff(v1 * 0.70710678118f));
                    *(uint32_t*)(C + (size_t)m * N + n) = pack_bf(v0, v1);
                }
            } else {
                float* C = (float*)Cv;
#pragma unroll
                for (int nt = 0; nt < 8; ++nt) {
                    int n = n0 + warp_n + nt*8 + 2*lt;
                    float v0 = acc[mt][nt][2*half];
                    float v1 = acc[mt][nt][2*half + 1];
                    float2 r2 = *(const float2*)(res + (size_t)m * N + n);
                    if (EPI == 3) { v0 += bias[n]; v1 += bias[n+1]; }
                    v0 += r2.x; v1 += r2.y;
                    *(float2*)(C + (size_t)m * N + n) = make_float2(v0, v1);
                }
            }
        }
    }
}

// ---------------- bf16 flash attention, cp.async double-buffered K/V ----------------
#define QPIT 72
#define PPIT 136
#define KV_STGB (128*QPIT*2)          // 18432 B
// layout: Q | K0 K1 | V0 V1 | P
#define FL_Q_OFF  0
#define FL_K_OFF  (128*QPIT)
#define FL_V_OFF  (FL_K_OFF + 2*128*QPIT)
#define FL_P_OFF  (FL_V_OFF + 2*128*QPIT)
#define FL_SMEM_BYTES ((FL_P_OFF + 128*PPIT) * 2)    // 126976 B

__global__ __launch_bounds__(256, 1) void flash_bf16_kernel(
    const uint16_t* __restrict__ Qg_, const uint16_t* __restrict__ Kg_,
    const uint16_t* __restrict__ Vg_, uint16_t* __restrict__ O)
{
    extern __shared__ uint16_t smb[];
    const uint32_t smBase = (uint32_t)__cvta_generic_to_shared(smb);
    const uint32_t qBase = smBase + 2*FL_Q_OFF;
    const uint32_t kBase = smBase + 2*FL_K_OFF;
    const uint32_t vBase = smBase + 2*FL_V_OFF;
    const uint32_t pBase = smBase + 2*FL_P_OFF;
    uint16_t* Qs = smb + FL_Q_OFF;
    uint16_t* Ps = smb + FL_P_OFF;

    const int tid  = threadIdx.x;
    const int warp = tid >> 5;
    const int lane = tid & 31;
    const int lg = lane >> 2;
    const int lt = lane & 3;
    const int warp_m = warp * 16;

    const int bh = blockIdx.y;
    const int qt = blockIdx.x;

    const uint16_t* Qg    = Qg_ + (size_t)bh * NSEQ * DH + (size_t)qt * 128 * DH;
    const uint16_t* Kbase = Kg_ + (size_t)bh * NSEQ * DH;
    const uint16_t* Vbase = Vg_ + (size_t)bh * NSEQ * DH;

    const int aRow = (lane & 15);
    const int aCol = (lane >> 4) * 8;
    const int bRow = (lane >> 4) * 8 + (lane & 7);
    const int bCol = ((lane >> 3) & 1) * 8;
    const int tRow = ((lane >> 3) & 1) * 8 + (lane & 7);
    const int tCol = (lane >> 4) * 8;

    auto issueKV = [&](int t, int s) {
        const uint16_t* Kt = Kbase + (size_t)t * 128 * DH;
        const uint16_t* Vt = Vbase + (size_t)t * 128 * DH;
#pragma unroll
        for (int it = 0; it < 4; ++it) {
            int c   = it * 256 + tid;
            int row = c >> 3;
            int ce  = (c & 7) * 8;
            cp16(kBase + s*KV_STGB + 2*(row*QPIT + ce), Kt + row*DH + ce);
            cp16(vBase + s*KV_STGB + 2*(row*QPIT + ce), Vt + row*DH + ce);
        }
    };

    // load Q (plain)
#pragma unroll
    for (int it = 0; it < 4; ++it) {
        int f  = it * 256 + tid;
        int r  = f >> 3;
        int c8 = (f & 7) * 8;
        *(uint4*)(&Qs[r*QPIT + c8]) = *(const uint4*)(Qg + r * DH + c8);
    }

    issueKV(0, 0); cpcommit();
    issueKV(1, 1); cpcommit();

    float m_i[2], l_i[2];
    m_i[0] = m_i[1] = -1e30f;
    l_i[0] = l_i[1] = 0.f;
    float oacc[8][4];
#pragma unroll
    for (int nt = 0; nt < 8; ++nt)
#pragma unroll
        for (int e = 0; e < 4; ++e) oacc[nt][e] = 0.f;

    const int NT = NSEQ / 128;   // 18
    for (int kt = 0; kt < NT; ++kt) {
        const int s = kt & 1;
        cpwait<1>();
        __syncthreads();

        // S = Q K^T : 16 rows x 128 keys
        float sacc[16][4];
#pragma unroll
        for (int nt = 0; nt < 16; ++nt)
#pragma unroll
            for (int e = 0; e < 4; ++e) sacc[nt][e] = 0.f;

#pragma unroll
        for (int ks = 0; ks < DH; ks += 16) {
            uint32_t af[4];
            ldsm4(af, qBase + 2*((warp_m + aRow)*QPIT + ks + aCol));
#pragma unroll
            for (int np = 0; np < 8; ++np) {
                uint32_t bf[4];
                ldsm4(bf, kBase + s*KV_STGB + 2*((np*16 + bRow)*QPIT + ks + bCol));
                mma_bf16(sacc[np*2],     af, bf);
                mma_bf16(sacc[np*2 + 1], af, bf + 2);
            }
        }

        // online softmax (warp-local rows)
#pragma unroll
        for (int half = 0; half < 2; ++half) {
            int rloc = warp_m + lg + half*8;
            float mx = -1e30f;
#pragma unroll
            for (int nt = 0; nt < 16; ++nt) {
                sacc[nt][2*half]     *= 0.125f;
                sacc[nt][2*half + 1] *= 0.125f;
                mx = fmaxf(mx, sacc[nt][2*half]);
                mx = fmaxf(mx, sacc[nt][2*half + 1]);
            }
            mx = fmaxf(mx, __shfl_xor_sync(0xffffffffu, mx, 1));
            mx = fmaxf(mx, __shfl_xor_sync(0xffffffffu, mx, 2));
            float mnew = fmaxf(m_i[half], mx);
            float corr = __expf(m_i[half] - mnew);
            m_i[half] = mnew;
            float sum = 0.f;
#pragma unroll
            for (int nt = 0; nt < 16; ++nt) {
                float p0 = __expf(sacc[nt][2*half]     - mnew);
                float p1 = __expf(sacc[nt][2*half + 1] - mnew);
                sum += p0 + p1;
                *(uint32_t*)(&Ps[rloc*PPIT + nt*8 + 2*lt]) = pack_bf(p0, p1);
            }
            sum += __shfl_xor_sync(0xffffffffu, sum, 1);
            sum += __shfl_xor_sync(0xffffffffu, sum, 2);
            l_i[half] = l_i[half] * corr + sum;
#pragma unroll
            for (int nt = 0; nt < 8; ++nt) {
                oacc[nt][2*half]     *= corr;
                oacc[nt][2*half + 1] *= corr;
            }
        }
        __syncwarp();

        // O += P V
#pragma unroll
        for (int ks = 0; ks < 128; ks += 16) {
            uint32_t af[4];
            ldsm4(af, pBase + 2*((warp_m + aRow)*PPIT + ks + aCol));
#pragma unroll
            for (int np = 0; np < 4; ++np) {
                uint32_t bf[4];
                ldsm4t(bf, vBase + s*KV_STGB + 2*((ks + tRow)*QPIT + np*16 + tCol));
                mma_bf16(oacc[np*2],     af, bf);
                mma_bf16(oacc[np*2 + 1], af, bf + 2);
            }
        }
        __syncthreads();
        if (kt + 2 < NT) issueKV(kt + 2, s);
        cpcommit();
    }

    // write O (bf16)
    const int b = bh >> 2, h = bh & 3;
#pragma unroll
    for (int half = 0; half < 2; ++half) {
        int row = qt * 128 + warp_m + lg + half*8;
        float inv = 1.0f / l_i[half];
        uint16_t* dst = O + ((size_t)(b * NSEQ + row)) * CDIM + h * DH;
#pragma unroll
        for (int nt = 0; nt < 8; ++nt)
            *(uint32_t*)(dst + nt*8 + 2*lt) =
                pack_bf(oacc[nt][2*half] * inv, oacc[nt][2*half + 1] * inv);
    }
}

// ---------------- layernorm over C=256: one warp per row ----------------
template<bool WRITE_BF>
__global__ __launch_bounds__(256) void ln_kernel(
    const float* __restrict__ x, float* __restrict__ y, uint16_t* __restrict__ ybf,
    const float* __restrict__ g, const float* __restrict__ b)
{
    const int warp = threadIdx.x >> 5;
    const int lane = threadIdx.x & 31;
    const int row  = blockIdx.x * 8 + warp;

    const float4* xr = (const float4*)(x + (size_t)row * CDIM) + lane * 2;
    float4 a = xr[0], c = xr[1];

    float s = a.x + a.y + a.z + a.w + c.x + c.y + c.z + c.w;
#pragma unroll
    for (int o = 16; o > 0; o >>= 1) s += __shfl_xor_sync(0xffffffffu, s, o);
    float mu = s * (1.0f / 256.0f);

    float d0 = a.x - mu, d1 = a.y - mu, d2 = a.z - mu, d3 = a.w - mu;
    float d4 = c.x - mu, d5 = c.y - mu, d6 = c.z - mu, d7 = c.w - mu;
    float q = d0*d0 + d1*d1 + d2*d2 + d3*d3 + d4*d4 + d5*d5 + d6*d6 + d7*d7;
#pragma unroll
    for (int o = 16; o > 0; o >>= 1) q += __shfl_xor_sync(0xffffffffu, q, o);
    float r = rsqrtf(q * (1.0f / 256.0f) + 1e-5f);

    const float4* gp = (const float4*)g + lane * 2;
    const float4* bp = (const float4*)b + lane * 2;
    float4 g0 = gp[0], g1 = gp[1], b0 = bp[0], b1 = bp[1];

    float o0 = d0*r*g0.x + b0.x, o1 = d1*r*g0.y + b0.y;
    float o2 = d2*r*g0.z + b0.z, o3 = d3*r*g0.w + b0.w;
    float o4 = d4*r*g1.x + b1.x, o5 = d5*r*g1.y + b1.y;
    float o6 = d6*r*g1.z + b1.z, o7 = d7*r*g1.w + b1.w;

    float4* yr = (float4*)(y + (size_t)row * CDIM) + lane * 2;
    yr[0] = make_float4(o0, o1, o2, o3);
    yr[1] = make_float4(o4, o5, o6, o7);
    if (WRITE_BF) {
        uint4 u = make_uint4(pack_bf(o0, o1), pack_bf(o2, o3), pack_bf(o4, o5), pack_bf(o6, o7));
        *(uint4*)(ybf + (size_t)row * CDIM + lane * 8) = u;
    }
}

// ---------------- launch ----------------
extern "C" void kernel_launch(void* const* d_in, const int* in_sizes, int n_in,
                              void* d_out, int out_size) {
    (void)in_sizes; (void)n_in; (void)out_size;
    const float* x     = (const float*)d_in[0];
    const float* Wqkv  = (const float*)d_in[1];
    const float* Wproj = (const float*)d_in[2];
    const float* g1    = (const float*)d_in[3];
    const float* b1    = (const float*)d_in[4];
    const float* g2    = (const float*)d_in[5];
    const float* b2    = (const float*)d_in[6];
    const float* W1    = (const float*)d_in[7];
    const float* bf1   = (const float*)d_in[8];
    const float* W2    = (const float*)d_in[9];
    const float* bf2   = (const float*)d_in[10];
    float* out = (float*)d_out;

    uint16_t *qkv, *xbf, *wbf, *attnbf, *x2bf, *hbf;
    float *x1, *x2;
    cudaGetSymbolAddress((void**)&qkv,    g_qkv);
    cudaGetSymbolAddress((void**)&xbf,    g_xbf);
    cudaGetSymbolAddress((void**)&wbf,    g_wbf);
    cudaGetSymbolAddress((void**)&attnbf, g_attnbf);
    cudaGetSymbolAddress((void**)&x2bf,   g_x2bf);
    cudaGetSymbolAddress((void**)&hbf,    g_hbf);
    cudaGetSymbolAddress((void**)&x1,     g_x1);
    cudaGetSymbolAddress((void**)&x2,     g_x2);

    cudaFuncSetAttribute(bgemm_kernel<0>, cudaFuncAttributeMaxDynamicSharedMemorySize, GEMM_SMEM);
    cudaFuncSetAttribute(bgemm_kernel<1>, cudaFuncAttributeMaxDynamicSharedMemorySize, GEMM_SMEM);
    cudaFuncSetAttribute(bgemm_kernel<2>, cudaFuncAttributeMaxDynamicSharedMemorySize, GEMM_SMEM);
    cudaFuncSetAttribute(bgemm_kernel<3>, cudaFuncAttributeMaxDynamicSharedMemorySize, GEMM_SMEM);
    cudaFuncSetAttribute(flash_bf16_kernel, cudaFuncAttributeMaxDynamicSharedMemorySize, FL_SMEM_BYTES);

    // 0. pre-convert x + weights to bf16
    cvt_kernel<<<(unsigned)((XE + WTOT_E) / 4 / 256), 256>>>(x, Wqkv, Wproj, W1, W2, xbf, wbf);

    // 1. QKV GEMM + RoPE -> bf16 scatter
    bgemm_kernel<0><<<dim3(768/128, MROWS/128), 256, GEMM_SMEM>>>(
        xbf, wbf + WQKV_OFF, qkv, MROWS, 768, CDIM, nullptr, nullptr);

    // 2. flash attention -> bf16
    flash_bf16_kernel<<<dim3(NSEQ/128, BATCH*NHEADS), 256, FL_SMEM_BYTES>>>(
        qkv, qkv + (size_t)QS, qkv + 2ull*QS, attnbf);

    // 3. proj + residual(x) -> f32 x1
    bgemm_kernel<1><<<dim3(CDIM/128, MROWS/128), 256, GEMM_SMEM>>>(
        attnbf, wbf + WPROJ_OFF, x1, MROWS, CDIM, CDIM, nullptr, x);

    // 4. LN1 -> f32 x2 + bf16 x2bf
    ln_kernel<true><<<MROWS/8, 256>>>(x1, x2, x2bf, g1, b1);

    // 5. MLP1: gelu(x2 @ W1^T + bf1) -> bf16 hbf
    bgemm_kernel<2><<<dim3(1024/128, MROWS/128), 256, GEMM_SMEM>>>(
        x2bf, wbf + W1_OFF, hbf, MROWS, 1024, CDIM, bf1, nullptr);

    // 6. MLP2: x2 + h @ W2^T + bf2 -> f32 x1
    bgemm_kernel<3><<<dim3(CDIM/128, MROWS/128), 256, GEMM_SMEM>>>(
        hbf, wbf + W2_OFF, x1, MROWS, CDIM, 1024, bf2, x2);

    // 7. LN2 -> out
    ln_kernel<false><<<MROWS/8, 256>>>(x1, out, nullptr, g2, b2);
}

// round 13
// speedup vs baseline: 6.0548x; 1.0774x over previous
#include <cuda_runtime.h>
#include <cuda_bf16.h>
#include <math.h>
#include <stdint.h>

// ---------------- problem constants ----------------
#define BATCH   4
#define NSEQ    2304          // 48*48
#define CDIM    256
#define NHEADS  4
#define DH      64
#define WIMG    48
#define MROWS   (BATCH*NSEQ)           // 9216
#define QS      (BATCH*NHEADS*NSEQ*DH) // 2359296 per q/k/v

// bf16 weight-pool offsets
#define WQKV_E  196608
#define WPROJ_E 65536
#define W1_E    262144
#define W2_E    262144
#define WQKV_OFF  0
#define WPROJ_OFF (WQKV_E)
#define W1_OFF    (WQKV_E + WPROJ_E)
#define W2_OFF    (WQKV_E + WPROJ_E + W1_E)
#define WTOT_E    (WQKV_E + WPROJ_E + W1_E + W2_E)   // 786432
#define XE        ((size_t)MROWS*CDIM)               // 2359296

// ---------------- scratch ----------------
__device__ uint16_t g_qkv[3ull*QS];
__device__ uint16_t g_xbf[XE];
__device__ uint16_t g_wbf[WTOT_E];
__device__ uint16_t g_attnbf[XE];
__device__ uint16_t g_x2bf[XE];
__device__ uint16_t g_hbf[(size_t)MROWS*4*CDIM];
__device__ float    g_x1[XE];
__device__ float    g_x2[XE];

// ---------------- helpers ----------------
__device__ __forceinline__ uint32_t pack_bf(float a, float b) {
    __nv_bfloat162 h = __floats2bfloat162_rn(a, b);
    return *reinterpret_cast<uint32_t*>(&h);
}
__device__ __forceinline__ void ldsm4(uint32_t* r, uint32_t addr) {
    asm volatile("ldmatrix.sync.aligned.m8n8.x4.shared.b16 {%0,%1,%2,%3}, [%4];"
        : "=r"(r[0]), "=r"(r[1]), "=r"(r[2]), "=r"(r[3]) : "r"(addr));
}
__device__ __forceinline__ void ldsm4t(uint32_t* r, uint32_t addr) {
    asm volatile("ldmatrix.sync.aligned.m8n8.x4.trans.shared.b16 {%0,%1,%2,%3}, [%4];"
        : "=r"(r[0]), "=r"(r[1]), "=r"(r[2]), "=r"(r[3]) : "r"(addr));
}
__device__ __forceinline__ void mma_bf16(float* d, const uint32_t* a, const uint32_t* b) {
    asm volatile(
        "mma.sync.aligned.m16n8k16.row.col.f32.bf16.bf16.f32 "
        "{%0,%1,%2,%3}, {%4,%5,%6,%7}, {%8,%9}, {%0,%1,%2,%3};\n"
        : "+f"(d[0]), "+f"(d[1]), "+f"(d[2]), "+f"(d[3])
        : "r"(a[0]), "r"(a[1]), "r"(a[2]), "r"(a[3]), "r"(b[0]), "r"(b[1]));
}
__device__ __forceinline__ void cp16(uint32_t smem, const void* g) {
    asm volatile("cp.async.cg.shared.global [%0], [%1], 16;" :: "r"(smem), "l"(g) : "memory");
}
__device__ __forceinline__ void cpcommit() { asm volatile("cp.async.commit_group;" ::: "memory"); }
template<int N> __device__ __forceinline__ void cpwait() {
    asm volatile("cp.async.wait_group %0;" :: "n"(N) : "memory");
}

// ---------------- f32 -> bf16 pre-convert ----------------
__global__ __launch_bounds__(256) void cvt_kernel(
    const float* __restrict__ x, const float* __restrict__ wqkv,
    const float* __restrict__ wproj, const float* __restrict__ w1,
    const float* __restrict__ w2,
    uint16_t* __restrict__ xbf, uint16_t* __restrict__ wbf)
{
    size_t e = ((size_t)blockIdx.x * 256 + threadIdx.x) * 4;
    const float* src; uint16_t* dst;
    if (e < XE) { src = x + e; dst = xbf + e; }
    else {
        size_t r = e - XE;
        dst = wbf + r;
        if      (r < WPROJ_OFF) src = wqkv  + r;
        else if (r < W1_OFF)    src = wproj + (r - WPROJ_OFF);
        else if (r < W2_OFF)    src = w1    + (r - W1_OFF);
        else                    src = w2    + (r - W2_OFF);
    }
    float4 v = *(const float4*)src;
    *(uint2*)dst = make_uint2(pack_bf(v.x, v.y), pack_bf(v.z, v.w));
}

// ---------------- bf16 pipelined GEMM: C = A(MxK) * B(NxK)^T ----------------
// EPI 0: rope->bf16 qkv (Q pre-scaled 0.125) | 1: +res f32 | 2: +bias gelu->bf16 | 3: +bias+res f32
#define BK   64
#define PIT  72

template<int EPI, int NTILE>
__global__ __launch_bounds__(256, 2) void bgemm_kernel(
    const uint16_t* __restrict__ A, const uint16_t* __restrict__ B, void* __restrict__ Cv,
    int M, int N, int K,
    const float* __restrict__ bias, const float* __restrict__ res)
{
    constexpr int WN   = NTILE / 2;      // warp n-extent: 64 or 32
    constexpr int NTPW = WN / 8;         // n-tiles per warp: 8 or 4
    constexpr int A_STGB = 128 * PIT * 2;
    constexpr int B_STGB = NTILE * PIT * 2;

    extern __shared__ uint16_t smg[];
    const uint32_t asBase = (uint32_t)__cvta_generic_to_shared(smg);
    const uint32_t bsBase = asBase + 2 * A_STGB;

    const int tid  = threadIdx.x;
    const int warp = tid >> 5;
    const int lane = tid & 31;
    const int m0 = blockIdx.y * 128;
    const int n0 = blockIdx.x * NTILE;
    const int warp_m = (warp & 3) * 32;
    const int warp_n = (warp >> 2) * WN;
    const int lg = lane >> 2;
    const int lt = lane & 3;

    const int aRow = (lane & 15);
    const int aCol = (lane >> 4) * 8;
    const int bRow = (lane >> 4) * 8 + (lane & 7);
    const int bCol = ((lane >> 3) & 1) * 8;

    const uint16_t* Ap0 = A + (size_t)m0 * K;
    const uint16_t* Bp0 = B + (size_t)n0 * K;
    const int nT = K / BK;

    auto issue = [&](int t, int s) {
        const int k0 = t * BK;
#pragma unroll
        for (int it = 0; it < 4; ++it) {
            int c   = it * 256 + tid;
            int row = c >> 3;
            int ce  = (c & 7) * 8;
            cp16(asBase + s*A_STGB + 2*(row*PIT + ce), Ap0 + (size_t)row*K + k0 + ce);
        }
#pragma unroll
        for (int it = 0; it < NTILE/32; ++it) {
            int c   = it * 256 + tid;
            int row = c >> 3;
            int ce  = (c & 7) * 8;
            cp16(bsBase + s*B_STGB + 2*(row*PIT + ce), Bp0 + (size_t)row*K + k0 + ce);
        }
    };

    float acc[2][NTPW][4];
#pragma unroll
    for (int mt = 0; mt < 2; ++mt)
#pragma unroll
        for (int nt = 0; nt < NTPW; ++nt)
#pragma unroll
            for (int e = 0; e < 4; ++e) acc[mt][nt][e] = 0.f;

    issue(0, 0); cpcommit();
    issue(1, 1); cpcommit();

    for (int t = 0; t < nT; ++t) {
        const int s = t & 1;
        cpwait<1>();
        __syncthreads();

#pragma unroll
        for (int ks = 0; ks < BK; ks += 16) {
            uint32_t af[2][4];
#pragma unroll
            for (int mt = 0; mt < 2; ++mt)
                ldsm4(af[mt], asBase + s*A_STGB + 2*((warp_m + mt*16 + aRow)*PIT + ks + aCol));
#pragma unroll
            for (int np = 0; np < NTPW/2; ++np) {
                uint32_t bf[4];
                ldsm4(bf, bsBase + s*B_STGB + 2*((warp_n + np*16 + bRow)*PIT + ks + bCol));
#pragma unroll
                for (int mt = 0; mt < 2; ++mt) {
                    mma_bf16(acc[mt][np*2],     af[mt], bf);
                    mma_bf16(acc[mt][np*2 + 1], af[mt], bf + 2);
                }
            }
        }
        __syncthreads();
        if (t + 2 < nT) issue(t + 2, s);
        cpcommit();
    }

    // ---------------- epilogue ----------------
#pragma unroll
    for (int mt = 0; mt < 2; ++mt) {
#pragma unroll
        for (int half = 0; half < 2; ++half) {
            int m = m0 + warp_m + mt*16 + lg + half*8;
            if (EPI == 0) {
                uint16_t* C = (uint16_t*)Cv;
                int b   = m / NSEQ;
                int pos = m - b * NSEQ;
                int yy  = pos / WIMG;
                int xx  = pos - yy * WIMG;
#pragma unroll
                for (int nt = 0; nt < NTPW; ++nt) {
                    int c = n0 + warp_n + nt*8 + 2*lt;
                    float v0 = acc[mt][nt][2*half];
                    float v1 = acc[mt][nt][2*half + 1];
                    int sel = c >> 8;
                    int rem = c & 255;
                    int h = rem >> 6;
                    int d = rem & 63;
                    if (sel < 2) {
                        float coord = (d < 32) ? (float)yy : (float)xx;
                        int j0 = d & 31;
                        float f0 = exp2f(-(float)j0 * 0.41524101186f);
                        float f1 = exp2f(-(float)(j0 + 1) * 0.41524101186f);
                        float s0, cv0, s1, cv1;
                        sincosf(coord * f0, &s0, &cv0);
                        sincosf(coord * f1, &s1, &cv1);
                        float w0 = v0 * cv0 - v1 * s0;
                        float w1 = v1 * cv1 + v0 * s1;
                        v0 = w0; v1 = w1;
                        if (sel == 0) { v0 *= 0.125f; v1 *= 0.125f; }  // fold 1/sqrt(dh)
                    }
                    size_t base = (size_t)sel * QS +
                                  ((size_t)(b * NHEADS + h) * NSEQ + pos) * DH + d;
                    *(uint32_t*)(C + base) = pack_bf(v0, v1);
                }
            } else if (EPI == 2) {
                uint16_t* C = (uint16_t*)Cv;
#pragma unroll
                for (int nt = 0; nt < NTPW; ++nt) {
                    int n = n0 + warp_n + nt*8 + 2*lt;
                    float v0 = acc[mt][nt][2*half] + bias[n];
                    float v1 = acc[mt][nt][2*half + 1] + bias[n+1];
                    v0 = 0.5f * v0 * (1.0f + erff(v0 * 0.70710678118f));
                    v1 = 0.5f * v1 * (1.0f + erff(v1 * 0.70710678118f));
                    *(uint32_t*)(C + (size_t)m * N + n) = pack_bf(v0, v1);
                }
            } else {
                float* C = (float*)Cv;
#pragma unroll
                for (int nt = 0; nt < NTPW; ++nt) {
                    int n = n0 + warp_n + nt*8 + 2*lt;
                    float v0 = acc[mt][nt][2*half];
                    float v1 = acc[mt][nt][2*half + 1];
                    float2 r2 = *(const float2*)(res + (size_t)m * N + n);
                    if (EPI == 3) { v0 += bias[n]; v1 += bias[n+1]; }
                    v0 += r2.x; v1 += r2.y;
                    *(float2*)(C + (size_t)m * N + n) = make_float2(v0, v1);
                }
            }
        }
    }
}
#define GEMM_SMEM_128 (4*128*PIT*2)            // 73728
#define GEMM_SMEM_64  (2*128*PIT*2 + 2*64*PIT*2) // 55296

// ---------------- bf16 flash attention: register-P, 2 CTAs/SM ----------------
#define QPIT 72
#define KV_STGB (128*QPIT*2)
#define FL_Q_OFF  0
#define FL_K_OFF  (128*QPIT)
#define FL_V_OFF  (FL_K_OFF + 2*128*QPIT)
#define FL_SMEM_BYTES ((FL_V_OFF + 2*128*QPIT) * 2)   // 92160 B

__global__ __launch_bounds__(256, 2) void flash_bf16_kernel(
    const uint16_t* __restrict__ Qg_, const uint16_t* __restrict__ Kg_,
    const uint16_t* __restrict__ Vg_, uint16_t* __restrict__ O)
{
    extern __shared__ uint16_t smb[];
    const uint32_t smBase = (uint32_t)__cvta_generic_to_shared(smb);
    const uint32_t qBase = smBase + 2*FL_Q_OFF;
    const uint32_t kBase = smBase + 2*FL_K_OFF;
    const uint32_t vBase = smBase + 2*FL_V_OFF;
    uint16_t* Qs = smb + FL_Q_OFF;

    const int tid  = threadIdx.x;
    const int warp = tid >> 5;
    const int lane = tid & 31;
    const int lg = lane >> 2;
    const int lt = lane & 3;
    const int warp_m = warp * 16;

    const int bh = blockIdx.y;
    const int qt = blockIdx.x;

    const uint16_t* Qg    = Qg_ + (size_t)bh * NSEQ * DH + (size_t)qt * 128 * DH;
    const uint16_t* Kbase = Kg_ + (size_t)bh * NSEQ * DH;
    const uint16_t* Vbase = Vg_ + (size_t)bh * NSEQ * DH;

    const int aRow = (lane & 15);
    const int aCol = (lane >> 4) * 8;
    const int bRow = (lane >> 4) * 8 + (lane & 7);
    const int bCol = ((lane >> 3) & 1) * 8;
    const int tRow = ((lane >> 3) & 1) * 8 + (lane & 7);
    const int tCol = (lane >> 4) * 8;

    auto issueKV = [&](int t, int s) {
        const uint16_t* Kt = Kbase + (size_t)t * 128 * DH;
        const uint16_t* Vt = Vbase + (size_t)t * 128 * DH;
#pragma unroll
        for (int it = 0; it < 4; ++it) {
            int c   = it * 256 + tid;
            int row = c >> 3;
            int ce  = (c & 7) * 8;
            cp16(kBase + s*KV_STGB + 2*(row*QPIT + ce), Kt + row*DH + ce);
            cp16(vBase + s*KV_STGB + 2*(row*QPIT + ce), Vt + row*DH + ce);
        }
    };

    // load Q (already scaled by 0.125 at QKV epilogue)
#pragma unroll
    for (int it = 0; it < 4; ++it) {
        int f  = it * 256 + tid;
        int r  = f >> 3;
        int c8 = (f & 7) * 8;
        *(uint4*)(&Qs[r*QPIT + c8]) = *(const uint4*)(Qg + r * DH + c8);
    }

    issueKV(0, 0); cpcommit();
    issueKV(1, 1); cpcommit();

    float m_i[2], l_i[2];
    m_i[0] = m_i[1] = -1e30f;
    l_i[0] = l_i[1] = 0.f;
    float oacc[8][4];
#pragma unroll
    for (int nt = 0; nt < 8; ++nt)
#pragma unroll
        for (int e = 0; e < 4; ++e) oacc[nt][e] = 0.f;

    const int NT = NSEQ / 128;   // 18
    for (int kt = 0; kt < NT; ++kt) {
        const int s = kt & 1;
        cpwait<1>();
        __syncthreads();

        // S = Q K^T : 16 rows x 128 keys
        float sacc[16][4];
#pragma unroll
        for (int nt = 0; nt < 16; ++nt)
#pragma unroll
            for (int e = 0; e < 4; ++e) sacc[nt][e] = 0.f;

#pragma unroll
        for (int ks = 0; ks < DH; ks += 16) {
            uint32_t af[4];
            ldsm4(af, qBase + 2*((warp_m + aRow)*QPIT + ks + aCol));
#pragma unroll
            for (int np = 0; np < 8; ++np) {
                uint32_t bf[4];
                ldsm4(bf, kBase + s*KV_STGB + 2*((np*16 + bRow)*QPIT + ks + bCol));
                mma_bf16(sacc[np*2],     af, bf);
                mma_bf16(sacc[np*2 + 1], af, bf + 2);
            }
        }

        // online softmax (warp-local rows); P packed straight into A-fragments
        uint32_t pf[16][2];
#pragma unroll
        for (int half = 0; half < 2; ++half) {
            float mx = -1e30f;
#pragma unroll
            for (int nt = 0; nt < 16; ++nt) {
                mx = fmaxf(mx, sacc[nt][2*half]);
                mx = fmaxf(mx, sacc[nt][2*half + 1]);
            }
            mx = fmaxf(mx, __shfl_xor_sync(0xffffffffu, mx, 1));
            mx = fmaxf(mx, __shfl_xor_sync(0xffffffffu, mx, 2));
            float mnew = fmaxf(m_i[half], mx);
            float corr = __expf(m_i[half] - mnew);
            m_i[half] = mnew;
            float sum = 0.f;
#pragma unroll
            for (int nt = 0; nt < 16; ++nt) {
                float p0 = __expf(sacc[nt][2*half]     - mnew);
                float p1 = __expf(sacc[nt][2*half + 1] - mnew);
                sum += p0 + p1;
                pf[nt][half] = pack_bf(p0, p1);
            }
            sum += __shfl_xor_sync(0xffffffffu, sum, 1);
            sum += __shfl_xor_sync(0xffffffffu, sum, 2);
            l_i[half] = l_i[half] * corr + sum;
#pragma unroll
            for (int nt = 0; nt < 8; ++nt) {
                oacc[nt][2*half]     *= corr;
                oacc[nt][2*half + 1] *= corr;
            }
        }

        // O += P V : P a-fragments direct from registers
#pragma unroll
        for (int kc = 0; kc < 8; ++kc) {
            uint32_t af[4] = { pf[2*kc][0], pf[2*kc][1], pf[2*kc+1][0], pf[2*kc+1][1] };
#pragma unroll
            for (int np = 0; np < 4; ++np) {
                uint32_t bf[4];
                ldsm4t(bf, vBase + s*KV_STGB + 2*((kc*16 + tRow)*QPIT + np*16 + tCol));
                mma_bf16(oacc[np*2],     af, bf);
                mma_bf16(oacc[np*2 + 1], af, bf + 2);
            }
        }
        __syncthreads();
        if (kt + 2 < NT) issueKV(kt + 2, s);
        cpcommit();
    }

    // write O (bf16)
    const int b = bh >> 2, h = bh & 3;
#pragma unroll
    for (int half = 0; half < 2; ++half) {
        int row = qt * 128 + warp_m + lg + half*8;
        float inv = 1.0f / l_i[half];
        uint16_t* dst = O + ((size_t)(b * NSEQ + row)) * CDIM + h * DH;
#pragma unroll
        for (int nt = 0; nt < 8; ++nt)
            *(uint32_t*)(dst + nt*8 + 2*lt) =
                pack_bf(oacc[nt][2*half] * inv, oacc[nt][2*half + 1] * inv);
    }
}

// ---------------- layernorm over C=256: one warp per row ----------------
template<bool WRITE_BF>
__global__ __launch_bounds__(256) void ln_kernel(
    const float* __restrict__ x, float* __restrict__ y, uint16_t* __restrict__ ybf,
    const float* __restrict__ g, const float* __restrict__ b)
{
    const int warp = threadIdx.x >> 5;
    const int lane = threadIdx.x & 31;
    const int row  = blockIdx.x * 8 + warp;

    const float4* xr = (const float4*)(x + (size_t)row * CDIM) + lane * 2;
    float4 a = xr[0], c = xr[1];

    float s = a.x + a.y + a.z + a.w + c.x + c.y + c.z + c.w;
#pragma unroll
    for (int o = 16; o > 0; o >>= 1) s += __shfl_xor_sync(0xffffffffu, s, o);
    float mu = s * (1.0f / 256.0f);

    float d0 = a.x - mu, d1 = a.y - mu, d2 = a.z - mu, d3 = a.w - mu;
    float d4 = c.x - mu, d5 = c.y - mu, d6 = c.z - mu, d7 = c.w - mu;
    float q = d0*d0 + d1*d1 + d2*d2 + d3*d3 + d4*d4 + d5*d5 + d6*d6 + d7*d7;
#pragma unroll
    for (int o = 16; o > 0; o >>= 1) q += __shfl_xor_sync(0xffffffffu, q, o);
    float r = rsqrtf(q * (1.0f / 256.0f) + 1e-5f);

    const float4* gp = (const float4*)g + lane * 2;
    const float4* bp = (const float4*)b + lane * 2;
    float4 g0 = gp[0], g1 = gp[1], b0 = bp[0], b1 = bp[1];

    float o0 = d0*r*g0.x + b0.x, o1 = d1*r*g0.y + b0.y;
    float o2 = d2*r*g0.z + b0.z, o3 = d3*r*g0.w + b0.w;
    float o4 = d4*r*g1.x + b1.x, o5 = d5*r*g1.y + b1.y;
    float o6 = d6*r*g1.z + b1.z, o7 = d7*r*g1.w + b1.w;

    float4* yr = (float4*)(y + (size_t)row * CDIM) + lane * 2;
    yr[0] = make_float4(o0, o1, o2, o3);
    yr[1] = make_float4(o4, o5, o6, o7);
    if (WRITE_BF) {
        uint4 u = make_uint4(pack_bf(o0, o1), pack_bf(o2, o3), pack_bf(o4, o5), pack_bf(o6, o7));
        *(uint4*)(ybf + (size_t)row * CDIM + lane * 8) = u;
    }
}

// ---------------- launch ----------------
extern "C" void kernel_launch(void* const* d_in, const int* in_sizes, int n_in,
                              void* d_out, int out_size) {
    (void)in_sizes; (void)n_in; (void)out_size;
    const float* x     = (const float*)d_in[0];
    const float* Wqkv  = (const float*)d_in[1];
    const float* Wproj = (const float*)d_in[2];
    const float* g1    = (const float*)d_in[3];
    const float* b1    = (const float*)d_in[4];
    const float* g2    = (const float*)d_in[5];
    const float* b2    = (const float*)d_in[6];
    const float* W1    = (const float*)d_in[7];
    const float* bf1   = (const float*)d_in[8];
    const float* W2    = (const float*)d_in[9];
    const float* bf2   = (const float*)d_in[10];
    float* out = (float*)d_out;

    uint16_t *qkv, *xbf, *wbf, *attnbf, *x2bf, *hbf;
    float *x1, *x2;
    cudaGetSymbolAddress((void**)&qkv,    g_qkv);
    cudaGetSymbolAddress((void**)&xbf,    g_xbf);
    cudaGetSymbolAddress((void**)&wbf,    g_wbf);
    cudaGetSymbolAddress((void**)&attnbf, g_attnbf);
    cudaGetSymbolAddress((void**)&x2bf,   g_x2bf);
    cudaGetSymbolAddress((void**)&hbf,    g_hbf);
    cudaGetSymbolAddress((void**)&x1,     g_x1);
    cudaGetSymbolAddress((void**)&x2,     g_x2);

    cudaFuncSetAttribute((const void*)bgemm_kernel<0,128>, cudaFuncAttributeMaxDynamicSharedMemorySize, GEMM_SMEM_128);
    cudaFuncSetAttribute((const void*)bgemm_kernel<2,128>, cudaFuncAttributeMaxDynamicSharedMemorySize, GEMM_SMEM_128);
    cudaFuncSetAttribute((const void*)bgemm_kernel<1,64>,  cudaFuncAttributeMaxDynamicSharedMemorySize, GEMM_SMEM_64);
    cudaFuncSetAttribute((const void*)bgemm_kernel<3,64>,  cudaFuncAttributeMaxDynamicSharedMemorySize, GEMM_SMEM_64);
    cudaFuncSetAttribute((const void*)flash_bf16_kernel,   cudaFuncAttributeMaxDynamicSharedMemorySize, FL_SMEM_BYTES);

    // 0. pre-convert x + weights to bf16
    cvt_kernel<<<(unsigned)((XE + WTOT_E) / 4 / 256), 256>>>(x, Wqkv, Wproj, W1, W2, xbf, wbf);

    // 1. QKV GEMM + RoPE (+0.125 on Q) -> bf16 scatter
    bgemm_kernel<0,128><<<dim3(768/128, MROWS/128), 256, GEMM_SMEM_128>>>(
        xbf, wbf + WQKV_OFF, qkv, MROWS, 768, CDIM, nullptr, nullptr);

    // 2. flash attention -> bf16
    flash_bf16_kernel<<<dim3(NSEQ/128, BATCH*NHEADS), 256, FL_SMEM_BYTES>>>(
        qkv, qkv + (size_t)QS, qkv + 2ull*QS, attnbf);

    // 3. proj + residual(x) -> f32 x1
    bgemm_kernel<1,64><<<dim3(CDIM/64, MROWS/128), 256, GEMM_SMEM_64>>>(
        attnbf, wbf + WPROJ_OFF, x1, MROWS, CDIM, CDIM, nullptr, x);

    // 4. LN1 -> f32 x2 + bf16 x2bf
    ln_kernel<true><<<MROWS/8, 256>>>(x1, x2, x2bf, g1, b1);

    // 5. MLP1: gelu(x2 @ W1^T + bf1) -> bf16 hbf
    bgemm_kernel<2,128><<<dim3(1024/128, MROWS/128), 256, GEMM_SMEM_128>>>(
        x2bf, wbf + W1_OFF, hbf, MROWS, 1024, CDIM, bf1, nullptr);

    // 6. MLP2: x2 + h @ W2^T + bf2 -> f32 x1
    bgemm_kernel<3,64><<<dim3(CDIM/64, MROWS/128), 256, GEMM_SMEM_64>>>(
        hbf, wbf + W2_OFF, x1, MROWS, CDIM, 1024, bf2, x2);

    // 7. LN2 -> out
    ln_kernel<false><<<MROWS/8, 256>>>(x1, out, nullptr, g2, b2);
}